// round 1
// baseline (speedup 1.0000x reference)
#include <cuda_runtime.h>
#include <math.h>

// ---------------- problem constants ----------------
static const int Bb   = 128;
static const int Ss   = 256;
static const int Dd   = 768;
static const int SPc  = 257;                 // S + 1 (head sentinel)
static const int NROWS = Bb * SPc;           // 32896 (= 514 * 64)
static const int ARCc = 500;
static const int TAGc = 100;
static const int TOPKc = 8;

// ---------------- scratch (device globals; no allocation allowed) ----------
__device__ float g_x  [NROWS * Dd];           // [N,768]
__device__ float g_ha [NROWS * ARCc];
__device__ float g_da [NROWS * ARCc];
__device__ float g_ht [NROWS * TAGc];
__device__ float g_dt [NROWS * TAGc];
__device__ float g_t1 [NROWS * (ARCc + 1)];   // bilinear intermediate [N,501]
__device__ float g_lg [Bb * SPc * SPc];       // logits / probs
__device__ float g_vals[NROWS * TOPKc];
__device__ int   g_idx [NROWS * TOPKc];       // local col j in [0,SP)
__device__ float g_dinv[NROWS];
__device__ float g_xw [NROWS * ARCc];         // conv scratch
__device__ float g_h  [NROWS * ARCc];         // conv scratch

// ---------------- kernels ----------------

// x = concat(sentinel, inputs) : one block per row
__global__ void build_x(const float* __restrict__ inp, const float* __restrict__ sent,
                        float* __restrict__ x) {
    int n = blockIdx.x;
    int b = n / SPc, r = n % SPc;
    const float* src = (r == 0) ? sent : (inp + ((size_t)b * Ss + (r - 1)) * Dd);
    float* dst = x + (size_t)n * Dd;
    for (int f = threadIdx.x; f < Dd; f += blockDim.x) dst[f] = src[f];
}

// C[M,N] = act(A[M,K] @ W[K,N](ld=ldw) + bias);   act: 0=none, 1=elu
__global__ void sgemm(const float* __restrict__ A, const float* __restrict__ W,
                      const float* __restrict__ bias, float* __restrict__ C,
                      int M, int N, int K, int ldw, int act) {
    __shared__ float As[16][64];
    __shared__ float Bs[16][65];
    int tid = threadIdx.x;
    int ty = tid >> 4, tx = tid & 15;
    int m0 = blockIdx.y * 64, n0 = blockIdx.x * 64;
    float acc[4][4];
#pragma unroll
    for (int i = 0; i < 4; i++)
#pragma unroll
        for (int j = 0; j < 4; j++) acc[i][j] = 0.f;

    for (int k0 = 0; k0 < K; k0 += 16) {
#pragma unroll
        for (int l = 0; l < 4; l++) {
            int id = tid + l * 256;
            int r = id >> 4, c = id & 15;          // A tile: 64 rows x 16 k
            int gm = m0 + r, gk = k0 + c;
            As[c][r] = (gm < M && gk < K) ? A[(size_t)gm * K + gk] : 0.f;
        }
#pragma unroll
        for (int l = 0; l < 4; l++) {
            int id = tid + l * 256;
            int r = id >> 6, c = id & 63;          // W tile: 16 k x 64 cols
            int gk = k0 + r, gn = n0 + c;
            Bs[r][c] = (gk < K && gn < N) ? W[(size_t)gk * ldw + gn] : 0.f;
        }
        __syncthreads();
#pragma unroll
        for (int kk = 0; kk < 16; kk++) {
            float a[4], bv[4];
#pragma unroll
            for (int i = 0; i < 4; i++) a[i] = As[kk][ty * 4 + i];
#pragma unroll
            for (int j = 0; j < 4; j++) bv[j] = Bs[kk][tx * 4 + j];
#pragma unroll
            for (int i = 0; i < 4; i++)
#pragma unroll
                for (int j = 0; j < 4; j++) acc[i][j] += a[i] * bv[j];
        }
        __syncthreads();
    }
#pragma unroll
    for (int i = 0; i < 4; i++) {
        int gm = m0 + ty * 4 + i;
        if (gm >= M) continue;
#pragma unroll
        for (int j = 0; j < 4; j++) {
            int gn = n0 + tx * 4 + j;
            if (gn >= N) continue;
            float v = acc[i][j];
            if (bias) v += bias[gn];
            if (act == 1) v = (v > 0.f) ? v : expm1f(v);
            C[(size_t)gm * N + gn] = v;
        }
    }
}

// logits[b,i,j] = sum_f t1[b,i,f]*da[b,j,f] (f<500) + t1[b,i,500] + bil_b[k]
__global__ void bil_nt(const float* __restrict__ T1, const float* __restrict__ DA,
                       const float* __restrict__ bilb, int kidx, float* __restrict__ Cout) {
    int bz = blockIdx.z;
    int i0 = blockIdx.y * 32, j0 = blockIdx.x * 32;
    __shared__ float As[32][33];
    __shared__ float Bs[32][33];
    int tid = threadIdx.x;
    int ty = tid >> 4, tx = tid & 15;
    const float* t1b = T1 + (size_t)bz * SPc * (ARCc + 1);
    const float* dab = DA + (size_t)bz * SPc * ARCc;
    float acc[2][2] = {{0.f, 0.f}, {0.f, 0.f}};

    for (int k0 = 0; k0 < ARCc; k0 += 32) {
#pragma unroll
        for (int l = 0; l < 4; l++) {
            int id = tid + l * 256;
            int r = id >> 5, c = id & 31;
            int gk = k0 + c;
            int gi = i0 + r;
            As[r][c] = (gi < SPc && gk < ARCc) ? t1b[(size_t)gi * (ARCc + 1) + gk] : 0.f;
            int gj = j0 + r;
            Bs[r][c] = (gj < SPc && gk < ARCc) ? dab[(size_t)gj * ARCc + gk] : 0.f;
        }
        __syncthreads();
#pragma unroll
        for (int kk = 0; kk < 32; kk++) {
            float a0 = As[ty * 2][kk], a1 = As[ty * 2 + 1][kk];
            float b0 = Bs[tx * 2][kk], b1 = Bs[tx * 2 + 1][kk];
            acc[0][0] += a0 * b0; acc[0][1] += a0 * b1;
            acc[1][0] += a1 * b0; acc[1][1] += a1 * b1;
        }
        __syncthreads();
    }
    float bb = bilb[kidx];
#pragma unroll
    for (int ii = 0; ii < 2; ii++) {
        int gi = i0 + ty * 2 + ii;
        if (gi >= SPc) continue;
        float t1bias = t1b[(size_t)gi * (ARCc + 1) + ARCc];
#pragma unroll
        for (int jj = 0; jj < 2; jj++) {
            int gj = j0 + tx * 2 + jj;
            if (gj >= SPc) continue;
            Cout[((size_t)bz * SPc + gi) * SPc + gj] = acc[ii][jj] + t1bias + bb;
        }
    }
}

// warp-per-row softmax over SP=257 columns, in place
__global__ void softmax_rows(float* __restrict__ lg) {
    int row = blockIdx.x * (blockDim.x >> 5) + (threadIdx.x >> 5);
    int lane = threadIdx.x & 31;
    if (row >= NROWS) return;
    float* p = lg + (size_t)row * SPc;
    float v[9];
    float mx = -INFINITY;
#pragma unroll
    for (int t = 0; t < 9; t++) {
        int c = lane + 32 * t;
        v[t] = (c < SPc) ? p[c] : -INFINITY;
        mx = fmaxf(mx, v[t]);
    }
#pragma unroll
    for (int off = 16; off > 0; off >>= 1) mx = fmaxf(mx, __shfl_xor_sync(0xffffffffu, mx, off));
    float s = 0.f;
#pragma unroll
    for (int t = 0; t < 9; t++) {
        int c = lane + 32 * t;
        if (c < SPc) { v[t] = expf(v[t] - mx); s += v[t]; }
    }
#pragma unroll
    for (int off = 16; off > 0; off >>= 1) s += __shfl_xor_sync(0xffffffffu, s, off);
    float inv = 1.f / s;
#pragma unroll
    for (int t = 0; t < 9; t++) {
        int c = lane + 32 * t;
        if (c < SPc) p[c] = v[t] * inv;
    }
}

// warp-per-row iterative top-8 (tie -> lowest index, matching lax.top_k)
__global__ void topk_rows(const float* __restrict__ lg) {
    int row = blockIdx.x * (blockDim.x >> 5) + (threadIdx.x >> 5);
    int lane = threadIdx.x & 31;
    if (row >= NROWS) return;
    const float* p = lg + (size_t)row * SPc;
    float v[9];
#pragma unroll
    for (int t = 0; t < 9; t++) {
        int c = lane + 32 * t;
        v[t] = (c < SPc) ? p[c] : -INFINITY;
    }
    for (int it = 0; it < TOPKc; it++) {
        float bv = -INFINITY; int bi = 0x7fffffff;
#pragma unroll
        for (int t = 0; t < 9; t++) {
            int c = lane + 32 * t;
            if (v[t] > bv || (v[t] == bv && c < bi)) { bv = v[t]; bi = c; }
        }
#pragma unroll
        for (int off = 16; off > 0; off >>= 1) {
            float ov = __shfl_down_sync(0xffffffffu, bv, off);
            int oi   = __shfl_down_sync(0xffffffffu, bi, off);
            if (ov > bv || (ov == bv && oi < bi)) { bv = ov; bi = oi; }
        }
        bv = __shfl_sync(0xffffffffu, bv, 0);
        bi = __shfl_sync(0xffffffffu, bi, 0);
        if (lane == 0) { g_vals[(size_t)row * TOPKc + it] = bv; g_idx[(size_t)row * TOPKc + it] = bi; }
        if (lane == (bi & 31)) v[bi >> 5] = -INFINITY;
    }
}

// deg[i] = 1 + sum(top8 vals);  dinv = rsqrt(deg)
__global__ void compute_dinv() {
    int i = blockIdx.x * blockDim.x + threadIdx.x;
    if (i >= NROWS) return;
    float s = 1.f;
#pragma unroll
    for (int k = 0; k < TOPKc; k++) s += g_vals[(size_t)i * TOPKc + k];
    g_dinv[i] = rsqrtf(s);
}

// out[i,:] = act( dinv[i]^2 * xw[i,:] + sum_k (dinv[i]*val*dinv[src]) * xw[src,:] + bias )
__global__ void gcn_agg(const float* __restrict__ xw, const float* __restrict__ bias,
                        float* __restrict__ out, int F, int act) {
    int i = blockIdx.x;
    int b = i / SPc;
    __shared__ float cf[TOPKc];
    __shared__ int   ss[TOPKc];
    float di = g_dinv[i];
    if (threadIdx.x < TOPKc) {
        int k = threadIdx.x;
        int src = b * SPc + g_idx[(size_t)i * TOPKc + k];
        ss[k] = src;
        cf[k] = di * g_vals[(size_t)i * TOPKc + k] * g_dinv[src];
    }
    __syncthreads();
    float selfc = di * di;
    const float* xwi = xw + (size_t)i * F;
    float* oi = out + (size_t)i * F;
    for (int f = threadIdx.x; f < F; f += blockDim.x) {
        float acc = selfc * xwi[f];
#pragma unroll
        for (int k = 0; k < TOPKc; k++) acc += cf[k] * xw[(size_t)ss[k] * F + f];
        acc += bias[f];
        if (act) acc = (acc > 0.f) ? acc : expm1f(acc);
        oi[f] = acc;
    }
}

__global__ void copyf(const float* __restrict__ src, float* __restrict__ dst, int n) {
    int i = blockIdx.x * blockDim.x + threadIdx.x;
    if (i < n) dst[i] = src[i];
}

// ---------------- launch ----------------
static inline void run_gemm(const float* A, const float* W, const float* bias, float* C,
                            int M, int N, int K, int ldw, int act) {
    dim3 grid((N + 63) / 64, M / 64);
    sgemm<<<grid, 256>>>(A, W, bias, C, M, N, K, ldw, act);
}

extern "C" void kernel_launch(void* const* d_in, const int* in_sizes, int n_in,
                              void* d_out, int out_size) {
    const float* inputs = (const float*)d_in[0];
    const float* sent   = (const float*)d_in[5];
    const float* W_ha = (const float*)d_in[6];  const float* b_ha = (const float*)d_in[7];
    const float* W_da = (const float*)d_in[8];  const float* b_da = (const float*)d_in[9];
    const float* W_ht = (const float*)d_in[10]; const float* b_ht = (const float*)d_in[11];
    const float* W_dt = (const float*)d_in[12]; const float* b_dt = (const float*)d_in[13];
    const float* bilW = (const float*)d_in[14]; const float* bilb = (const float*)d_in[15];
    const float* c1aW = (const float*)d_in[16]; const float* c1ab = (const float*)d_in[17];
    const float* c2aW = (const float*)d_in[18]; const float* c2ab = (const float*)d_in[19];
    const float* c1rW = (const float*)d_in[20]; const float* c1rb = (const float*)d_in[21];
    const float* c2rW = (const float*)d_in[22]; const float* c2rb = (const float*)d_in[23];
    float* out = (float*)d_out;

    float *x, *ha, *da, *ht, *dt, *t1, *lg, *xw, *h;
    cudaGetSymbolAddress((void**)&x,  g_x);
    cudaGetSymbolAddress((void**)&ha, g_ha);
    cudaGetSymbolAddress((void**)&da, g_da);
    cudaGetSymbolAddress((void**)&ht, g_ht);
    cudaGetSymbolAddress((void**)&dt, g_dt);
    cudaGetSymbolAddress((void**)&t1, g_t1);
    cudaGetSymbolAddress((void**)&lg, g_lg);
    cudaGetSymbolAddress((void**)&xw, g_xw);
    cudaGetSymbolAddress((void**)&h,  g_h);

    // 1) x = [sentinel ; inputs]
    build_x<<<NROWS, 256>>>(inputs, sent, x);

    // 2) projections with ELU
    run_gemm(x, W_ha, b_ha, ha, NROWS, ARCc, Dd, ARCc, 1);
    run_gemm(x, W_da, b_da, da, NROWS, ARCc, Dd, ARCc, 1);
    run_gemm(x, W_ht, b_ht, ht, NROWS, TAGc, Dd, TAGc, 1);
    run_gemm(x, W_dt, b_dt, dt, NROWS, TAGc, Dd, TAGc, 1);

    int nwarps_grid = NROWS / 8;   // 4112 blocks of 8 warps
    dim3 bilgrid((SPc + 31) / 32, (SPc + 31) / 32, Bb);

    for (int k = 0; k < 2; k++) {
        const float* Wk = bilW + (size_t)k * (ARCc + 1) * (ARCc + 1);
        // t1 = head_arc @ Wk[0:500,:] + Wk[500,:]
        run_gemm(ha, Wk, Wk + (size_t)ARCc * (ARCc + 1), t1, NROWS, ARCc + 1, ARCc, ARCc + 1, 0);
        bil_nt<<<bilgrid, 256>>>(t1, da, bilb, k, lg);
        softmax_rows<<<nwarps_grid, 256>>>(lg);
        topk_rows<<<nwarps_grid, 256>>>(lg);
        compute_dinv<<<(NROWS + 255) / 256, 256>>>();

        // two_conv on each feature stream (arc streams share c1a/c2a, tag streams c1r/c2r)
        float* feats[4] = {ha, da, ht, dt};
        const float* W1s[4] = {c1aW, c1aW, c1rW, c1rW};
        const float* b1s[4] = {c1ab, c1ab, c1rb, c1rb};
        const float* W2s[4] = {c2aW, c2aW, c2rW, c2rW};
        const float* b2s[4] = {c2ab, c2ab, c2rb, c2rb};
        int Fs[4] = {ARCc, ARCc, TAGc, TAGc};
        for (int s = 0; s < 4; s++) {
            int F = Fs[s];
            run_gemm(feats[s], W1s[s], nullptr, xw, NROWS, F, F, F, 0);
            gcn_agg<<<NROWS, 128>>>(xw, b1s[s], h, F, 1);       // + elu (between convs)
            run_gemm(h, W2s[s], nullptr, xw, NROWS, F, F, F, 0);
            gcn_agg<<<NROWS, 128>>>(xw, b2s[s], feats[s], F, 0); // overwrite feature
        }
    }

    // final bilinear (layer index 2) -> arc_logits directly into d_out
    {
        const float* Wk = bilW + (size_t)2 * (ARCc + 1) * (ARCc + 1);
        run_gemm(ha, Wk, Wk + (size_t)ARCc * (ARCc + 1), t1, NROWS, ARCc + 1, ARCc, ARCc + 1, 0);
        bil_nt<<<bilgrid, 256>>>(t1, da, bilb, 2, out);
    }

    // append head_tag, dep_tag
    int arcN = Bb * SPc * SPc;
    int tagN = NROWS * TAGc;
    if (out_size >= arcN + 2 * tagN) {
        copyf<<<(tagN + 255) / 256, 256>>>(ht, out + arcN, tagN);
        copyf<<<(tagN + 255) / 256, 256>>>(dt, out + arcN + tagN, tagN);
    }
}

// round 3
// speedup vs baseline: 1.0451x; 1.0451x over previous
#include <cuda_runtime.h>
#include <math.h>
#include <mma.h>
using namespace nvcuda;

// ---------------- problem constants ----------------
static const int Bb   = 128;
static const int Ss   = 256;
static const int Dd   = 768;
static const int SPc  = 257;                 // S + 1
static const int NROWS = Bb * SPc;           // 32896 = 128 * 257
static const int ARCc = 500;
static const int TAGc = 100;
static const int TOPKc = 8;
static const int ARCP = 512;                 // padded arc dim
static const int TAGP = 128;                 // padded tag dim

// ---------------- scratch ----------------
__device__ float g_x   [NROWS * Dd];
__device__ float g_arc [2 * NROWS * ARCP];    // [ha ; da]
__device__ float g_tag [2 * NROWS * TAGP];    // [ht ; dt]
__device__ float g_t1  [NROWS * ARCP];        // bilinear intermediate (501 valid)
__device__ float g_lg  [Bb * SPc * SPc];
__device__ float g_vals[NROWS * TOPKc];
__device__ int   g_idx [NROWS * TOPKc];
__device__ float g_dinv[NROWS];
__device__ float g_xw  [2 * NROWS * ARCP];    // conv scratch
__device__ float g_h   [2 * NROWS * ARCP];    // conv scratch

// split helpers: x = hi + lo with hi,lo representable in tf32
__device__ __forceinline__ float tf32_hi(float x) { return wmma::__float_to_tf32(x); }

// ---------------- kernels ----------------

__global__ void build_x(const float* __restrict__ inp, const float* __restrict__ sent,
                        float* __restrict__ x) {
    int n = blockIdx.x;
    int b = n / SPc, r = n % SPc;
    const float* src = (r == 0) ? sent : (inp + ((size_t)b * Ss + (r - 1)) * Dd);
    float* dst = x + (size_t)n * Dd;
    for (int f = threadIdx.x; f < Dd; f += blockDim.x) dst[f] = src[f];
}

// C[M, Npad] = A[M,Kpad](lda) @ W[Wrows,Wcols](ldw, zero-padded to Kpad x Npad)
// 3xTF32 split for ~fp32 accuracy on the tensor pipe.
// M multiple of 128, Npad multiple of 64, Kpad multiple of 32, lda multiple of 4.
__global__ void gemm_3xtf32(const float* __restrict__ A, int lda,
                            const float* __restrict__ W, int ldw, int Wrows, int Wcols,
                            float* __restrict__ C, int ldc, int Kpad) {
    __shared__ float As[128][40];
    __shared__ float Bs[32][72];
    int tid = threadIdx.x;
    int warp = tid >> 5;
    int wm = warp & 3;            // 4 warps in M dir (32 rows each)
    int wn = warp >> 2;           // 2 warps in N dir (32 cols each)
    int m0 = blockIdx.y * 128, n0 = blockIdx.x * 64;

    wmma::fragment<wmma::accumulator, 16, 16, 8, float> c[2][2];
#pragma unroll
    for (int i = 0; i < 2; i++)
#pragma unroll
        for (int j = 0; j < 2; j++) wmma::fill_fragment(c[i][j], 0.f);

    for (int k0 = 0; k0 < Kpad; k0 += 32) {
        // A tile 128x32 via float4 (4 per thread)
#pragma unroll
        for (int l = 0; l < 4; l++) {
            int id = tid + l * 256;
            int r = id >> 3, c4 = id & 7;
            float4 v = *(const float4*)(A + (size_t)(m0 + r) * lda + k0 + c4 * 4);
            *(float4*)&As[r][c4 * 4] = v;
        }
        // W tile 32x64, guarded scalar (8 per thread)
#pragma unroll
        for (int l = 0; l < 8; l++) {
            int id = tid + l * 256;
            int r = id >> 6, cc = id & 63;
            int gk = k0 + r, gn = n0 + cc;
            Bs[r][cc] = (gk < Wrows && gn < Wcols) ? W[(size_t)gk * ldw + gn] : 0.f;
        }
        __syncthreads();
#pragma unroll
        for (int ks = 0; ks < 4; ks++) {
            wmma::fragment<wmma::matrix_a, 16, 16, 8, wmma::precision::tf32, wmma::row_major> ah[2], al[2];
            wmma::fragment<wmma::matrix_b, 16, 16, 8, wmma::precision::tf32, wmma::row_major> bh[2], bl[2];
#pragma unroll
            for (int i = 0; i < 2; i++) {
                wmma::load_matrix_sync(ah[i], &As[wm * 32 + i * 16][ks * 8], 40);
#pragma unroll
                for (int t = 0; t < ah[i].num_elements; t++) {
                    float x = ah[i].x[t];
                    float hi = tf32_hi(x);
                    ah[i].x[t] = hi;
                    al[i].x[t] = tf32_hi(x - hi);
                }
            }
#pragma unroll
            for (int j = 0; j < 2; j++) {
                wmma::load_matrix_sync(bh[j], &Bs[ks * 8][wn * 32 + j * 16], 72);
#pragma unroll
                for (int t = 0; t < bh[j].num_elements; t++) {
                    float x = bh[j].x[t];
                    float hi = tf32_hi(x);
                    bh[j].x[t] = hi;
                    bl[j].x[t] = tf32_hi(x - hi);
                }
            }
#pragma unroll
            for (int i = 0; i < 2; i++)
#pragma unroll
                for (int j = 0; j < 2; j++) {
                    wmma::mma_sync(c[i][j], al[i], bh[j], c[i][j]);
                    wmma::mma_sync(c[i][j], ah[i], bl[j], c[i][j]);
                    wmma::mma_sync(c[i][j], ah[i], bh[j], c[i][j]);
                }
        }
        __syncthreads();
    }
#pragma unroll
    for (int i = 0; i < 2; i++)
#pragma unroll
        for (int j = 0; j < 2; j++)
            wmma::store_matrix_sync(C + (size_t)(m0 + wm * 32 + i * 16) * ldc + n0 + wn * 32 + j * 16,
                                    c[i][j], ldc, wmma::mem_row_major);
}

// elementwise bias (+optional elu) over [rows, ld]; bias applied for col < valid
__global__ void bias_act(float* __restrict__ C, const float* __restrict__ bias,
                         int ld, int valid, long total, int act) {
    long i = (long)blockIdx.x * blockDim.x + threadIdx.x;
    if (i >= total) return;
    int n = (int)(i % ld);
    float v = C[i];
    if (n < valid) v += bias[n];
    if (act) v = (v > 0.f) ? v : expm1f(v);
    C[i] = v;
}

// batched bilinear NT (3xTF32): out[b,i,j] = sum_f t1[b,i,f]*da[b,j,f] + t1[b,i,500] + bilb
__global__ void bil_nt_3xtf32(const float* __restrict__ T1, const float* __restrict__ DA,
                              const float* __restrict__ bilb, int kidx, float* __restrict__ Cout) {
    __shared__ float As[64][40];
    __shared__ float Bs[32][72];
    __shared__ float Cs[64][68];
    int bz = blockIdx.z;
    int i0 = blockIdx.y * 64, j0 = blockIdx.x * 64;
    int tid = threadIdx.x;
    int warp = tid >> 5;
    int wm = warp & 3;            // 4 warps x 16 rows = 64
    int wn = warp >> 2;           // 2 warps x 32 cols = 64
    const float* t1b = T1 + (size_t)bz * SPc * ARCP;
    const float* dab = DA + (size_t)bz * SPc * ARCP;

    wmma::fragment<wmma::accumulator, 16, 16, 8, float> c[2];
    wmma::fill_fragment(c[0], 0.f);
    wmma::fill_fragment(c[1], 0.f);

    for (int k0 = 0; k0 < ARCP; k0 += 32) {
        // A tile 64x32 (rows guarded)
#pragma unroll
        for (int l = 0; l < 2; l++) {
            int id = tid + l * 256;
            int r = id >> 3, c4 = id & 7;
            int gi = i0 + r;
            float4 v = make_float4(0.f, 0.f, 0.f, 0.f);
            if (gi < SPc) v = *(const float4*)(t1b + (size_t)gi * ARCP + k0 + c4 * 4);
            *(float4*)&As[r][c4 * 4] = v;
        }
        // B tile: Bs[k][j] = da[j0+j][k0+k], j guarded
#pragma unroll
        for (int l = 0; l < 8; l++) {
            int id = tid + l * 256;
            int r = id >> 6, cc = id & 63;
            int gj = j0 + cc;
            Bs[r][cc] = (gj < SPc) ? dab[(size_t)gj * ARCP + k0 + r] : 0.f;
        }
        __syncthreads();
#pragma unroll
        for (int ks = 0; ks < 4; ks++) {
            wmma::fragment<wmma::matrix_a, 16, 16, 8, wmma::precision::tf32, wmma::row_major> ah, al;
            wmma::fragment<wmma::matrix_b, 16, 16, 8, wmma::precision::tf32, wmma::row_major> bh[2], bl[2];
            wmma::load_matrix_sync(ah, &As[wm * 16][ks * 8], 40);
#pragma unroll
            for (int t = 0; t < ah.num_elements; t++) {
                float x = ah.x[t];
                float hi = tf32_hi(x);
                ah.x[t] = hi;
                al.x[t] = tf32_hi(x - hi);
            }
#pragma unroll
            for (int j = 0; j < 2; j++) {
                wmma::load_matrix_sync(bh[j], &Bs[ks * 8][wn * 32 + j * 16], 72);
#pragma unroll
                for (int t = 0; t < bh[j].num_elements; t++) {
                    float x = bh[j].x[t];
                    float hi = tf32_hi(x);
                    bh[j].x[t] = hi;
                    bl[j].x[t] = tf32_hi(x - hi);
                }
            }
#pragma unroll
            for (int j = 0; j < 2; j++) {
                wmma::mma_sync(c[j], al, bh[j], c[j]);
                wmma::mma_sync(c[j], ah, bl[j], c[j]);
                wmma::mma_sync(c[j], ah, bh[j], c[j]);
            }
        }
        __syncthreads();
    }
    wmma::store_matrix_sync(&Cs[wm * 16][wn * 32], c[0], 68, wmma::mem_row_major);
    wmma::store_matrix_sync(&Cs[wm * 16][wn * 32 + 16], c[1], 68, wmma::mem_row_major);
    __syncthreads();
    float bb = bilb[kidx];
#pragma unroll
    for (int l = 0; l < 16; l++) {
        int id = tid + l * 256;
        int r = id >> 6, cc = id & 63;
        int gi = i0 + r, gj = j0 + cc;
        if (gi < SPc && gj < SPc)
            Cout[((size_t)bz * SPc + gi) * SPc + gj] = Cs[r][cc] + t1b[(size_t)gi * ARCP + ARCc] + bb;
    }
}

// warp-per-row softmax over SP=257, in place
__global__ void softmax_rows(float* __restrict__ lg) {
    int row = blockIdx.x * (blockDim.x >> 5) + (threadIdx.x >> 5);
    int lane = threadIdx.x & 31;
    if (row >= NROWS) return;
    float* p = lg + (size_t)row * SPc;
    float v[9];
    float mx = -INFINITY;
#pragma unroll
    for (int t = 0; t < 9; t++) {
        int c = lane + 32 * t;
        v[t] = (c < SPc) ? p[c] : -INFINITY;
        mx = fmaxf(mx, v[t]);
    }
#pragma unroll
    for (int off = 16; off > 0; off >>= 1) mx = fmaxf(mx, __shfl_xor_sync(0xffffffffu, mx, off));
    float s = 0.f;
#pragma unroll
    for (int t = 0; t < 9; t++) {
        int c = lane + 32 * t;
        if (c < SPc) { v[t] = expf(v[t] - mx); s += v[t]; }
    }
#pragma unroll
    for (int off = 16; off > 0; off >>= 1) s += __shfl_xor_sync(0xffffffffu, s, off);
    float inv = 1.f / s;
#pragma unroll
    for (int t = 0; t < 9; t++) {
        int c = lane + 32 * t;
        if (c < SPc) p[c] = v[t] * inv;
    }
}

// warp-per-row iterative top-8 (tie -> lowest index)
__global__ void topk_rows(const float* __restrict__ lg) {
    int row = blockIdx.x * (blockDim.x >> 5) + (threadIdx.x >> 5);
    int lane = threadIdx.x & 31;
    if (row >= NROWS) return;
    const float* p = lg + (size_t)row * SPc;
    float v[9];
#pragma unroll
    for (int t = 0; t < 9; t++) {
        int c = lane + 32 * t;
        v[t] = (c < SPc) ? p[c] : -INFINITY;
    }
    for (int it = 0; it < TOPKc; it++) {
        float bv = -INFINITY; int bi = 0x7fffffff;
#pragma unroll
        for (int t = 0; t < 9; t++) {
            int c = lane + 32 * t;
            if (v[t] > bv || (v[t] == bv && c < bi)) { bv = v[t]; bi = c; }
        }
#pragma unroll
        for (int off = 16; off > 0; off >>= 1) {
            float ov = __shfl_down_sync(0xffffffffu, bv, off);
            int oi   = __shfl_down_sync(0xffffffffu, bi, off);
            if (ov > bv || (ov == bv && oi < bi)) { bv = ov; bi = oi; }
        }
        bv = __shfl_sync(0xffffffffu, bv, 0);
        bi = __shfl_sync(0xffffffffu, bi, 0);
        if (lane == 0) { g_vals[(size_t)row * TOPKc + it] = bv; g_idx[(size_t)row * TOPKc + it] = bi; }
        if (lane == (bi & 31)) v[bi >> 5] = -INFINITY;
    }
}

__global__ void compute_dinv() {
    int i = blockIdx.x * blockDim.x + threadIdx.x;
    if (i >= NROWS) return;
    float s = 1.f;
#pragma unroll
    for (int k = 0; k < TOPKc; k++) s += g_vals[(size_t)i * TOPKc + k];
    g_dinv[i] = rsqrtf(s);
}

// dual-stream GCN aggregate over padded feature dim Fp (valid Fv for bias)
__global__ void gcn_agg(const float* __restrict__ xw, const float* __restrict__ bias,
                        float* __restrict__ out, int Fp, int Fv, int act) {
    int gid = blockIdx.x;
    int i = gid % NROWS;
    int stream = gid / NROWS;
    int b = i / SPc;
    __shared__ float cf[TOPKc];
    __shared__ int   ss[TOPKc];
    float di = g_dinv[i];
    if (threadIdx.x < TOPKc) {
        int k = threadIdx.x;
        int srow = b * SPc + g_idx[(size_t)i * TOPKc + k];
        ss[k] = stream * NROWS + srow;
        cf[k] = di * g_vals[(size_t)i * TOPKc + k] * g_dinv[srow];
    }
    __syncthreads();
    float selfc = di * di;
    const float* xwi = xw + (size_t)gid * Fp;
    float* oi = out + (size_t)gid * Fp;
    for (int f = threadIdx.x; f < Fp; f += blockDim.x) {
        float acc = selfc * xwi[f];
#pragma unroll
        for (int k = 0; k < TOPKc; k++) acc += cf[k] * xw[(size_t)ss[k] * Fp + f];
        if (f < Fv) acc += bias[f];
        if (act) acc = (acc > 0.f) ? acc : expm1f(acc);
        oi[f] = acc;
    }
}

// strided copy: dst[n*valid + f] = src[n*ld + f]
__global__ void copy_strided(const float* __restrict__ src, float* __restrict__ dst,
                             int ld, int valid, int rows) {
    long i = (long)blockIdx.x * blockDim.x + threadIdx.x;
    long total = (long)rows * valid;
    if (i >= total) return;
    int n = (int)(i / valid), f = (int)(i % valid);
    dst[i] = src[(size_t)n * ld + f];
}

// ---------------- launch ----------------
static inline void run_gemm(const float* A, int lda, const float* W, int ldw,
                            int Wrows, int Wcols, float* C, int M, int Npad, int Kpad) {
    dim3 grid(Npad / 64, M / 128);
    gemm_3xtf32<<<grid, 256>>>(A, lda, W, ldw, Wrows, Wcols, C, Npad, Kpad);
}

extern "C" void kernel_launch(void* const* d_in, const int* in_sizes, int n_in,
                              void* d_out, int out_size) {
    const float* inputs = (const float*)d_in[0];
    const float* sent   = (const float*)d_in[5];
    const float* W_ha = (const float*)d_in[6];  const float* b_ha = (const float*)d_in[7];
    const float* W_da = (const float*)d_in[8];  const float* b_da = (const float*)d_in[9];
    const float* W_ht = (const float*)d_in[10]; const float* b_ht = (const float*)d_in[11];
    const float* W_dt = (const float*)d_in[12]; const float* b_dt = (const float*)d_in[13];
    const float* bilW = (const float*)d_in[14]; const float* bilb = (const float*)d_in[15];
    const float* c1aW = (const float*)d_in[16]; const float* c1ab = (const float*)d_in[17];
    const float* c2aW = (const float*)d_in[18]; const float* c2ab = (const float*)d_in[19];
    const float* c1rW = (const float*)d_in[20]; const float* c1rb = (const float*)d_in[21];
    const float* c2rW = (const float*)d_in[22]; const float* c2rb = (const float*)d_in[23];
    float* out = (float*)d_out;

    float *x, *arc, *tag, *t1, *lg, *xw, *h;
    cudaGetSymbolAddress((void**)&x,   g_x);
    cudaGetSymbolAddress((void**)&arc, g_arc);
    cudaGetSymbolAddress((void**)&tag, g_tag);
    cudaGetSymbolAddress((void**)&t1,  g_t1);
    cudaGetSymbolAddress((void**)&lg,  g_lg);
    cudaGetSymbolAddress((void**)&xw,  g_xw);
    cudaGetSymbolAddress((void**)&h,   g_h);

    float* ha = arc;
    float* da = arc + (size_t)NROWS * ARCP;
    float* ht = tag;
    float* dt = tag + (size_t)NROWS * TAGP;

    // 1) x = [sentinel ; inputs]
    build_x<<<NROWS, 256>>>(inputs, sent, x);

    // 2) projections + ELU
    run_gemm(x, Dd, W_ha, ARCc, Dd, ARCc, ha, NROWS, ARCP, Dd);
    run_gemm(x, Dd, W_da, ARCc, Dd, ARCc, da, NROWS, ARCP, Dd);
    run_gemm(x, Dd, W_ht, TAGc, Dd, TAGc, ht, NROWS, TAGP, Dd);
    run_gemm(x, Dd, W_dt, TAGc, Dd, TAGc, dt, NROWS, TAGP, Dd);
    long arcTot = (long)NROWS * ARCP, tagTot = (long)NROWS * TAGP;
    bias_act<<<(unsigned)((arcTot + 255) / 256), 256>>>(ha, b_ha, ARCP, ARCc, arcTot, 1);
    bias_act<<<(unsigned)((arcTot + 255) / 256), 256>>>(da, b_da, ARCP, ARCc, arcTot, 1);
    bias_act<<<(unsigned)((tagTot + 255) / 256), 256>>>(ht, b_ht, TAGP, TAGc, tagTot, 1);
    bias_act<<<(unsigned)((tagTot + 255) / 256), 256>>>(dt, b_dt, TAGP, TAGc, tagTot, 1);

    int nwarps_grid = NROWS / 8;
    dim3 bilgrid((SPc + 63) / 64, (SPc + 63) / 64, Bb);

    for (int k = 0; k < 2; k++) {
        const float* Wk = bilW + (size_t)k * (ARCc + 1) * (ARCc + 1);
        // t1 = ha @ Wk[0:500,:] (+ Wk[500,:] bias)
        run_gemm(ha, ARCP, Wk, ARCc + 1, ARCc, ARCc + 1, t1, NROWS, ARCP, ARCP);
        bias_act<<<(unsigned)((arcTot + 255) / 256), 256>>>(t1, Wk + (size_t)ARCc * (ARCc + 1), ARCP, ARCc + 1, arcTot, 0);
        bil_nt_3xtf32<<<bilgrid, 256>>>(t1, da, bilb, k, lg);
        softmax_rows<<<nwarps_grid, 256>>>(lg);
        topk_rows<<<nwarps_grid, 256>>>(lg);
        compute_dinv<<<(NROWS + 255) / 256, 256>>>();

        // arc streams: one GEMM over [2*NROWS, 512]
        run_gemm(arc, ARCP, c1aW, ARCc, ARCc, ARCc, xw, 2 * NROWS, ARCP, ARCP);
        gcn_agg<<<2 * NROWS, 128>>>(xw, c1ab, h, ARCP, ARCc, 1);
        run_gemm(h, ARCP, c2aW, ARCc, ARCc, ARCc, xw, 2 * NROWS, ARCP, ARCP);
        gcn_agg<<<2 * NROWS, 128>>>(xw, c2ab, arc, ARCP, ARCc, 0);
        // tag streams: one GEMM over [2*NROWS, 128]
        run_gemm(tag, TAGP, c1rW, TAGc, TAGc, TAGc, xw, 2 * NROWS, TAGP, TAGP);
        gcn_agg<<<2 * NROWS, 128>>>(xw, c1rb, h, TAGP, TAGc, 1);
        run_gemm(h, TAGP, c2rW, TAGc, TAGc, TAGc, xw, 2 * NROWS, TAGP, TAGP);
        gcn_agg<<<2 * NROWS, 128>>>(xw, c2rb, tag, TAGP, TAGc, 0);
    }

    // final bilinear -> d_out
    {
        const float* Wk = bilW + (size_t)2 * (ARCc + 1) * (ARCc + 1);
        run_gemm(ha, ARCP, Wk, ARCc + 1, ARCc, ARCc + 1, t1, NROWS, ARCP, ARCP);
        bias_act<<<(unsigned)((arcTot + 255) / 256), 256>>>(t1, Wk + (size_t)ARCc * (ARCc + 1), ARCP, ARCc + 1, arcTot, 0);
        bil_nt_3xtf32<<<bilgrid, 256>>>(t1, da, bilb, 2, out);
    }

    // append head_tag, dep_tag (unpad 128 -> 100)
    long arcN = (long)Bb * SPc * SPc;
    long tagN = (long)NROWS * TAGc;
    copy_strided<<<(unsigned)((tagN + 255) / 256), 256>>>(ht, out + arcN, TAGP, TAGc, NROWS);
    copy_strided<<<(unsigned)((tagN + 255) / 256), 256>>>(dt, out + arcN + tagN, TAGP, TAGc, NROWS);
}

// round 4
// speedup vs baseline: 2.6835x; 2.5678x over previous
#include <cuda_runtime.h>
#include <cuda_bf16.h>
#include <math.h>
#include <mma.h>
using namespace nvcuda;

// ---------------- problem constants ----------------
static const int Bb   = 128;
static const int Ss   = 256;
static const int Dd   = 768;
static const int SPc  = 257;
static const int NROWS = Bb * SPc;           // 32896 = 257*128
static const int ARCc = 500;
static const int TAGc = 100;
static const int TOPKc = 8;
static const int ARCP = 512;
static const int TAGP = 128;
static const int GEMM_SMEM = (4 * 128 * 40 + 4 * 32 * 72) * 2;  // 59392 B

// ---------------- fp32 scratch ----------------
__device__ float g_arc [2 * NROWS * ARCP];    // [ha ; da] fp32 (pre-split staging)
__device__ float g_tag [2 * NROWS * TAGP];    // [ht ; dt] fp32
__device__ float g_t1  [NROWS * ARCP];
__device__ float g_lg  [Bb * SPc * SPc];
__device__ float g_xw  [2 * NROWS * ARCP];
__device__ float g_vals[NROWS * TOPKc];
__device__ int   g_idx [NROWS * TOPKc];
__device__ float g_dinv[NROWS];

// ---------------- bf16 hi/lo planes ----------------
__device__ __nv_bfloat16 g_xH[NROWS * Dd],        g_xL[NROWS * Dd];
__device__ __nv_bfloat16 g_arcH[2 * NROWS * ARCP], g_arcL[2 * NROWS * ARCP];
__device__ __nv_bfloat16 g_tagH[2 * NROWS * TAGP], g_tagL[2 * NROWS * TAGP];
__device__ __nv_bfloat16 g_t1H[NROWS * ARCP],      g_t1L[NROWS * ARCP];
__device__ __nv_bfloat16 g_hH[2 * NROWS * ARCP],   g_hL[2 * NROWS * ARCP];
// weights (padded, split)
__device__ __nv_bfloat16 g_whaH[768 * 512], g_whaL[768 * 512];
__device__ __nv_bfloat16 g_wdaH[768 * 512], g_wdaL[768 * 512];
__device__ __nv_bfloat16 g_whtH[768 * 128], g_whtL[768 * 128];
__device__ __nv_bfloat16 g_wdtH[768 * 128], g_wdtL[768 * 128];
__device__ __nv_bfloat16 g_bilH[3 * 512 * 512], g_bilL[3 * 512 * 512];
__device__ __nv_bfloat16 g_c1aH[512 * 512], g_c1aL[512 * 512];
__device__ __nv_bfloat16 g_c2aH[512 * 512], g_c2aL[512 * 512];
__device__ __nv_bfloat16 g_c1rH[128 * 128], g_c1rL[128 * 128];
__device__ __nv_bfloat16 g_c2rH[128 * 128], g_c2rL[128 * 128];

__device__ __forceinline__ void splitbf(float v, __nv_bfloat16& h, __nv_bfloat16& l) {
    h = __float2bfloat16(v);
    l = __float2bfloat16(v - __bfloat162float(h));
}

// ---------------- small kernels ----------------

__global__ void pad_split_w(const float* __restrict__ W, int Wr, int Wc, int ldw,
                            __nv_bfloat16* __restrict__ hi, __nv_bfloat16* __restrict__ lo,
                            int Kp, int Np) {
    int i = blockIdx.x * blockDim.x + threadIdx.x;
    if (i >= Kp * Np) return;
    int r = i / Np, c = i % Np;
    float v = (r < Wr && c < Wc) ? W[(size_t)r * ldw + c] : 0.f;
    splitbf(v, hi[i], lo[i]);
}

__global__ void build_x_split(const float* __restrict__ inp, const float* __restrict__ sent,
                              __nv_bfloat16* __restrict__ xh, __nv_bfloat16* __restrict__ xl) {
    int n = blockIdx.x;
    int b = n / SPc, r = n % SPc;
    const float* src = (r == 0) ? sent : (inp + ((size_t)b * Ss + (r - 1)) * Dd);
    for (int f = threadIdx.x; f < Dd; f += blockDim.x) {
        splitbf(src[f], xh[(size_t)n * Dd + f], xl[(size_t)n * Dd + f]);
    }
}

__global__ void bias_act_split(float* __restrict__ C, const float* __restrict__ bias,
                               __nv_bfloat16* __restrict__ hi, __nv_bfloat16* __restrict__ lo,
                               int ld, int valid, long total, int act) {
    long i = (long)blockIdx.x * blockDim.x + threadIdx.x;
    if (i >= total) return;
    int n = (int)(i % ld);
    float v = C[i];
    if (n < valid) v += bias[n];
    if (act) v = (v > 0.f) ? v : expm1f(v);
    C[i] = v;
    splitbf(v, hi[i], lo[i]);
}

// ---------------- main GEMM: 3xBF16 split, cp.async double-buffered ----------------
// C[M, Npad] = (Ah+Al)[M,Kpad](lda) @ (Bh+Bl)[Kpad,Npad](ldb), fp32 accum (lo*lo dropped)

__device__ __forceinline__ void gemm_load_stage(
    const __nv_bfloat16* __restrict__ Ah, const __nv_bfloat16* __restrict__ Al, int lda,
    const __nv_bfloat16* __restrict__ Bh, const __nv_bfloat16* __restrict__ Bl, int ldb,
    __nv_bfloat16* sA0, __nv_bfloat16* sA1, __nv_bfloat16* sB0, __nv_bfloat16* sB1,
    int m0, int n0, int k0, int tid)
{
#pragma unroll
    for (int l = 0; l < 2; l++) {
        int c = tid + l * 256;
        int r = c >> 2, co = (c & 3) * 8;
        const __nv_bfloat16* gh = Ah + (size_t)(m0 + r) * lda + k0 + co;
        const __nv_bfloat16* gl = Al + (size_t)(m0 + r) * lda + k0 + co;
        unsigned dh = (unsigned)__cvta_generic_to_shared(sA0 + r * 40 + co);
        unsigned dl = (unsigned)__cvta_generic_to_shared(sA1 + r * 40 + co);
        asm volatile("cp.async.cg.shared.global [%0], [%1], 16;" :: "r"(dh), "l"(gh));
        asm volatile("cp.async.cg.shared.global [%0], [%1], 16;" :: "r"(dl), "l"(gl));
    }
    {
        int kk = tid >> 3, co = (tid & 7) * 8;
        const __nv_bfloat16* gh = Bh + (size_t)(k0 + kk) * ldb + n0 + co;
        const __nv_bfloat16* gl = Bl + (size_t)(k0 + kk) * ldb + n0 + co;
        unsigned dh = (unsigned)__cvta_generic_to_shared(sB0 + kk * 72 + co);
        unsigned dl = (unsigned)__cvta_generic_to_shared(sB1 + kk * 72 + co);
        asm volatile("cp.async.cg.shared.global [%0], [%1], 16;" :: "r"(dh), "l"(gh));
        asm volatile("cp.async.cg.shared.global [%0], [%1], 16;" :: "r"(dl), "l"(gl));
    }
    asm volatile("cp.async.commit_group;");
}

__global__ void __launch_bounds__(256, 2)
gemm_bf16x3(const __nv_bfloat16* __restrict__ Ah, const __nv_bfloat16* __restrict__ Al, int lda,
            const __nv_bfloat16* __restrict__ Bh, const __nv_bfloat16* __restrict__ Bl, int ldb,
            float* __restrict__ C, int ldc, int Kpad) {
    extern __shared__ __nv_bfloat16 sm[];
    const int ASZ = 128 * 40, BSZ = 32 * 72;
    __nv_bfloat16* sA[2][2];
    __nv_bfloat16* sB[2][2];
#pragma unroll
    for (int st = 0; st < 2; st++)
#pragma unroll
        for (int pl = 0; pl < 2; pl++) {
            sA[st][pl] = sm + (st * 2 + pl) * ASZ;
            sB[st][pl] = sm + 4 * ASZ + (st * 2 + pl) * BSZ;
        }
    int tid = threadIdx.x;
    int warp = tid >> 5;
    int wm = warp & 3, wn = warp >> 2;
    int m0 = blockIdx.y * 128, n0 = blockIdx.x * 64;

    wmma::fragment<wmma::accumulator, 16, 16, 16, float> acc[2][2];
#pragma unroll
    for (int i = 0; i < 2; i++)
#pragma unroll
        for (int j = 0; j < 2; j++) wmma::fill_fragment(acc[i][j], 0.f);

    int nk = Kpad >> 5;
    gemm_load_stage(Ah, Al, lda, Bh, Bl, ldb, sA[0][0], sA[0][1], sB[0][0], sB[0][1], m0, n0, 0, tid);

    for (int kt = 0; kt < nk; kt++) {
        if (kt + 1 < nk) {
            int st = (kt + 1) & 1;
            gemm_load_stage(Ah, Al, lda, Bh, Bl, ldb, sA[st][0], sA[st][1], sB[st][0], sB[st][1],
                            m0, n0, (kt + 1) << 5, tid);
            asm volatile("cp.async.wait_group 1;");
        } else {
            asm volatile("cp.async.wait_group 0;");
        }
        __syncthreads();
        int st = kt & 1;
#pragma unroll
        for (int ks = 0; ks < 2; ks++) {
            wmma::fragment<wmma::matrix_a, 16, 16, 16, __nv_bfloat16, wmma::row_major> fah[2], fal[2];
            wmma::fragment<wmma::matrix_b, 16, 16, 16, __nv_bfloat16, wmma::row_major> fbh[2], fbl[2];
#pragma unroll
            for (int i = 0; i < 2; i++) {
                wmma::load_matrix_sync(fah[i], sA[st][0] + (wm * 32 + i * 16) * 40 + ks * 16, 40);
                wmma::load_matrix_sync(fal[i], sA[st][1] + (wm * 32 + i * 16) * 40 + ks * 16, 40);
            }
#pragma unroll
            for (int j = 0; j < 2; j++) {
                wmma::load_matrix_sync(fbh[j], sB[st][0] + (ks * 16) * 72 + wn * 32 + j * 16, 72);
                wmma::load_matrix_sync(fbl[j], sB[st][1] + (ks * 16) * 72 + wn * 32 + j * 16, 72);
            }
#pragma unroll
            for (int i = 0; i < 2; i++)
#pragma unroll
                for (int j = 0; j < 2; j++) {
                    wmma::mma_sync(acc[i][j], fal[i], fbh[j], acc[i][j]);
                    wmma::mma_sync(acc[i][j], fah[i], fbl[j], acc[i][j]);
                    wmma::mma_sync(acc[i][j], fah[i], fbh[j], acc[i][j]);
                }
        }
        __syncthreads();
    }
#pragma unroll
    for (int i = 0; i < 2; i++)
#pragma unroll
        for (int j = 0; j < 2; j++)
            wmma::store_matrix_sync(C + (size_t)(m0 + wm * 32 + i * 16) * ldc + n0 + wn * 32 + j * 16,
                                    acc[i][j], ldc, wmma::mem_row_major);
}

// ---------------- batched bilinear NT (3xBF16, col-major B frags) ----------------
__global__ void bil_nt_bf16x3(const __nv_bfloat16* __restrict__ t1h, const __nv_bfloat16* __restrict__ t1l,
                              const float* __restrict__ t1f,
                              const __nv_bfloat16* __restrict__ dah, const __nv_bfloat16* __restrict__ dal,
                              const float* __restrict__ bilb, int kidx, float* __restrict__ Cout) {
    __shared__ __nv_bfloat16 As[2][64][40];
    __shared__ __nv_bfloat16 Bs[2][64][40];
    __shared__ float Cs[64][68];
    int bz = blockIdx.z;
    int i0 = blockIdx.y * 64, j0 = blockIdx.x * 64;
    int tid = threadIdx.x, warp = tid >> 5;
    int wm = warp & 3, wn = warp >> 2;
    size_t aoff = (size_t)bz * SPc * ARCP;

    wmma::fragment<wmma::accumulator, 16, 16, 16, float> acc[2];
    wmma::fill_fragment(acc[0], 0.f);
    wmma::fill_fragment(acc[1], 0.f);

    int r = tid >> 2, co = (tid & 3) * 8;
    int gi = i0 + r, gj = j0 + r;

    for (int k0 = 0; k0 < ARCP; k0 += 32) {
        uint4 z = make_uint4(0, 0, 0, 0);
        uint4 vh = (gi < SPc) ? *(const uint4*)(t1h + aoff + (size_t)gi * ARCP + k0 + co) : z;
        uint4 vl = (gi < SPc) ? *(const uint4*)(t1l + aoff + (size_t)gi * ARCP + k0 + co) : z;
        uint4 wh = (gj < SPc) ? *(const uint4*)(dah + aoff + (size_t)gj * ARCP + k0 + co) : z;
        uint4 wl = (gj < SPc) ? *(const uint4*)(dal + aoff + (size_t)gj * ARCP + k0 + co) : z;
        *(uint4*)&As[0][r][co] = vh;
        *(uint4*)&As[1][r][co] = vl;
        *(uint4*)&Bs[0][r][co] = wh;
        *(uint4*)&Bs[1][r][co] = wl;
        __syncthreads();
#pragma unroll
        for (int ks = 0; ks < 2; ks++) {
            wmma::fragment<wmma::matrix_a, 16, 16, 16, __nv_bfloat16, wmma::row_major> fah, fal;
            wmma::fragment<wmma::matrix_b, 16, 16, 16, __nv_bfloat16, wmma::col_major> fbh[2], fbl[2];
            wmma::load_matrix_sync(fah, &As[0][wm * 16][ks * 16], 40);
            wmma::load_matrix_sync(fal, &As[1][wm * 16][ks * 16], 40);
#pragma unroll
            for (int j = 0; j < 2; j++) {
                wmma::load_matrix_sync(fbh[j], &Bs[0][wn * 32 + j * 16][ks * 16], 40);
                wmma::load_matrix_sync(fbl[j], &Bs[1][wn * 32 + j * 16][ks * 16], 40);
            }
#pragma unroll
            for (int j = 0; j < 2; j++) {
                wmma::mma_sync(acc[j], fal, fbh[j], acc[j]);
                wmma::mma_sync(acc[j], fah, fbl[j], acc[j]);
                wmma::mma_sync(acc[j], fah, fbh[j], acc[j]);
            }
        }
        __syncthreads();
    }
    wmma::store_matrix_sync(&Cs[wm * 16][wn * 32], acc[0], 68, wmma::mem_row_major);
    wmma::store_matrix_sync(&Cs[wm * 16][wn * 32 + 16], acc[1], 68, wmma::mem_row_major);
    __syncthreads();
    float bb = bilb[kidx];
#pragma unroll
    for (int l = 0; l < 16; l++) {
        int id = tid + l * 256;
        int rr = id >> 6, cc = id & 63;
        int oi = i0 + rr, oj = j0 + cc;
        if (oi < SPc && oj < SPc)
            Cout[((size_t)bz * SPc + oi) * SPc + oj] =
                Cs[rr][cc] + t1f[aoff + (size_t)oi * ARCP + ARCc] + bb;
    }
}

// ---------------- fused softmax + top-8 + dinv (warp per row) ----------------
__global__ void smax_topk(const float* __restrict__ lg) {
    int row = blockIdx.x * 8 + (threadIdx.x >> 5);
    int lane = threadIdx.x & 31;
    if (row >= NROWS) return;
    const float* p = lg + (size_t)row * SPc;
    float v[9];
    float mx = -INFINITY;
#pragma unroll
    for (int t = 0; t < 9; t++) {
        int c = lane + 32 * t;
        v[t] = (c < SPc) ? p[c] : -INFINITY;
        mx = fmaxf(mx, v[t]);
    }
#pragma unroll
    for (int off = 16; off > 0; off >>= 1) mx = fmaxf(mx, __shfl_xor_sync(0xffffffffu, mx, off));
    float s = 0.f;
#pragma unroll
    for (int t = 0; t < 9; t++) {
        int c = lane + 32 * t;
        if (c < SPc) { v[t] = expf(v[t] - mx); s += v[t]; } else v[t] = -INFINITY;
    }
#pragma unroll
    for (int off = 16; off > 0; off >>= 1) s += __shfl_xor_sync(0xffffffffu, s, off);
    float inv = 1.f / s;
#pragma unroll
    for (int t = 0; t < 9; t++) {
        int c = lane + 32 * t;
        if (c < SPc) v[t] *= inv;
    }
    float acc8 = 0.f;
    for (int it = 0; it < TOPKc; it++) {
        float bv = -INFINITY; int bi = 0x7fffffff;
#pragma unroll
        for (int t = 0; t < 9; t++) {
            int c = lane + 32 * t;
            if (v[t] > bv || (v[t] == bv && c < bi)) { bv = v[t]; bi = c; }
        }
#pragma unroll
        for (int off = 16; off > 0; off >>= 1) {
            float ov = __shfl_down_sync(0xffffffffu, bv, off);
            int oi   = __shfl_down_sync(0xffffffffu, bi, off);
            if (ov > bv || (ov == bv && oi < bi)) { bv = ov; bi = oi; }
        }
        bv = __shfl_sync(0xffffffffu, bv, 0);
        bi = __shfl_sync(0xffffffffu, bi, 0);
        if (lane == 0) { g_vals[(size_t)row * TOPKc + it] = bv; g_idx[(size_t)row * TOPKc + it] = bi; }
        acc8 += bv;
        if (lane == (bi & 31)) v[bi >> 5] = -INFINITY;
    }
    if (lane == 0) g_dinv[row] = rsqrtf(1.f + acc8);
}

// ---------------- GCN aggregate + ELU + split (dual stream) ----------------
__global__ void gcn_agg_split(const float* __restrict__ xw, const float* __restrict__ bias,
                              float* __restrict__ outf,
                              __nv_bfloat16* __restrict__ outh, __nv_bfloat16* __restrict__ outl,
                              int Fp, int Fv, int act) {
    int gid = blockIdx.x;
    int i = gid % NROWS;
    int stream = gid / NROWS;
    int b = i / SPc;
    __shared__ float cf[TOPKc];
    __shared__ int   ss[TOPKc];
    float di = g_dinv[i];
    if (threadIdx.x < TOPKc) {
        int k = threadIdx.x;
        int srow = b * SPc + g_idx[(size_t)i * TOPKc + k];
        ss[k] = stream * NROWS + srow;
        cf[k] = di * g_vals[(size_t)i * TOPKc + k] * g_dinv[srow];
    }
    __syncthreads();
    float selfc = di * di;
    const float* xwi = xw + (size_t)gid * Fp;
    for (int f = threadIdx.x; f < Fp; f += blockDim.x) {
        float acc = selfc * xwi[f];
#pragma unroll
        for (int k = 0; k < TOPKc; k++) acc += cf[k] * xw[(size_t)ss[k] * Fp + f];
        if (f < Fv) acc += bias[f];
        if (act) acc = (acc > 0.f) ? acc : expm1f(acc);
        size_t o = (size_t)gid * Fp + f;
        if (outf) outf[o] = acc;
        splitbf(acc, outh[o], outl[o]);
    }
}

__global__ void copy_strided(const float* __restrict__ src, float* __restrict__ dst,
                             int ld, int valid, int rows) {
    long i = (long)blockIdx.x * blockDim.x + threadIdx.x;
    long total = (long)rows * valid;
    if (i >= total) return;
    int n = (int)(i / valid), f = (int)(i % valid);
    dst[i] = src[(size_t)n * ld + f];
}

// ---------------- host ----------------
template <typename T>
static T* sym(const void* s) { void* p; cudaGetSymbolAddress(&p, s); return (T*)p; }

static void run_gemm(const __nv_bfloat16* Ah, const __nv_bfloat16* Al, int lda,
                     const __nv_bfloat16* Bh, const __nv_bfloat16* Bl, int Npad,
                     float* C, int M, int Kpad) {
    dim3 grid(Npad / 64, M / 128);
    gemm_bf16x3<<<grid, 256, GEMM_SMEM>>>(Ah, Al, lda, Bh, Bl, Npad, C, Npad, Kpad);
}

extern "C" void kernel_launch(void* const* d_in, const int* in_sizes, int n_in,
                              void* d_out, int out_size) {
    const float* inputs = (const float*)d_in[0];
    const float* sent   = (const float*)d_in[5];
    const float* W_ha = (const float*)d_in[6];  const float* b_ha = (const float*)d_in[7];
    const float* W_da = (const float*)d_in[8];  const float* b_da = (const float*)d_in[9];
    const float* W_ht = (const float*)d_in[10]; const float* b_ht = (const float*)d_in[11];
    const float* W_dt = (const float*)d_in[12]; const float* b_dt = (const float*)d_in[13];
    const float* bilW = (const float*)d_in[14]; const float* bilb = (const float*)d_in[15];
    const float* c1aW = (const float*)d_in[16]; const float* c1ab = (const float*)d_in[17];
    const float* c2aW = (const float*)d_in[18]; const float* c2ab = (const float*)d_in[19];
    const float* c1rW = (const float*)d_in[20]; const float* c1rb = (const float*)d_in[21];
    const float* c2rW = (const float*)d_in[22]; const float* c2rb = (const float*)d_in[23];
    float* out = (float*)d_out;

    cudaFuncSetAttribute(gemm_bf16x3, cudaFuncAttributeMaxDynamicSharedMemorySize, GEMM_SMEM);

    float* arcF = sym<float>(g_arc);
    float* tagF = sym<float>(g_tag);
    float* t1F  = sym<float>(g_t1);
    float* lg   = sym<float>(g_lg);
    float* xw   = sym<float>(g_xw);
    __nv_bfloat16 *xH = sym<__nv_bfloat16>(g_xH), *xL = sym<__nv_bfloat16>(g_xL);
    __nv_bfloat16 *arcH = sym<__nv_bfloat16>(g_arcH), *arcL = sym<__nv_bfloat16>(g_arcL);
    __nv_bfloat16 *tagH = sym<__nv_bfloat16>(g_tagH), *tagL = sym<__nv_bfloat16>(g_tagL);
    __nv_bfloat16 *t1H = sym<__nv_bfloat16>(g_t1H), *t1L = sym<__nv_bfloat16>(g_t1L);
    __nv_bfloat16 *hH = sym<__nv_bfloat16>(g_hH), *hL = sym<__nv_bfloat16>(g_hL);
    __nv_bfloat16 *whaH = sym<__nv_bfloat16>(g_whaH), *whaL = sym<__nv_bfloat16>(g_whaL);
    __nv_bfloat16 *wdaH = sym<__nv_bfloat16>(g_wdaH), *wdaL = sym<__nv_bfloat16>(g_wdaL);
    __nv_bfloat16 *whtH = sym<__nv_bfloat16>(g_whtH), *whtL = sym<__nv_bfloat16>(g_whtL);
    __nv_bfloat16 *wdtH = sym<__nv_bfloat16>(g_wdtH), *wdtL = sym<__nv_bfloat16>(g_wdtL);
    __nv_bfloat16 *bilH = sym<__nv_bfloat16>(g_bilH), *bilL = sym<__nv_bfloat16>(g_bilL);
    __nv_bfloat16 *c1aH = sym<__nv_bfloat16>(g_c1aH), *c1aL = sym<__nv_bfloat16>(g_c1aL);
    __nv_bfloat16 *c2aH = sym<__nv_bfloat16>(g_c2aH), *c2aL = sym<__nv_bfloat16>(g_c2aL);
    __nv_bfloat16 *c1rH = sym<__nv_bfloat16>(g_c1rH), *c1rL = sym<__nv_bfloat16>(g_c1rL);
    __nv_bfloat16 *c2rH = sym<__nv_bfloat16>(g_c2rH), *c2rL = sym<__nv_bfloat16>(g_c2rL);

    float* haF = arcF;
    float* daF = arcF + (size_t)NROWS * ARCP;
    __nv_bfloat16 *haH = arcH, *haL = arcL;
    __nv_bfloat16 *daH = arcH + (size_t)NROWS * ARCP, *daL = arcL + (size_t)NROWS * ARCP;
    float* htF = tagF;
    float* dtF = tagF + (size_t)NROWS * TAGP;
    __nv_bfloat16 *htH = tagH, *htL = tagL;
    __nv_bfloat16 *dtH = tagH + (size_t)NROWS * TAGP, *dtL = tagL + (size_t)NROWS * TAGP;

    // --- weight pad + split ---
    pad_split_w<<<(768 * 512 + 255) / 256, 256>>>(W_ha, 768, 500, 500, whaH, whaL, 768, 512);
    pad_split_w<<<(768 * 512 + 255) / 256, 256>>>(W_da, 768, 500, 500, wdaH, wdaL, 768, 512);
    pad_split_w<<<(768 * 128 + 255) / 256, 256>>>(W_ht, 768, 100, 100, whtH, whtL, 768, 128);
    pad_split_w<<<(768 * 128 + 255) / 256, 256>>>(W_dt, 768, 100, 100, wdtH, wdtL, 768, 128);
    for (int k = 0; k < 3; k++)
        pad_split_w<<<(512 * 512 + 255) / 256, 256>>>(bilW + (size_t)k * 501 * 501, 500, 501, 501,
                                                      bilH + (size_t)k * 512 * 512, bilL + (size_t)k * 512 * 512, 512, 512);
    pad_split_w<<<(512 * 512 + 255) / 256, 256>>>(c1aW, 500, 500, 500, c1aH, c1aL, 512, 512);
    pad_split_w<<<(512 * 512 + 255) / 256, 256>>>(c2aW, 500, 500, 500, c2aH, c2aL, 512, 512);
    pad_split_w<<<(128 * 128 + 255) / 256, 256>>>(c1rW, 100, 100, 100, c1rH, c1rL, 128, 128);
    pad_split_w<<<(128 * 128 + 255) / 256, 256>>>(c2rW, 100, 100, 100, c2rH, c2rL, 128, 128);

    // --- x + projections ---
    build_x_split<<<NROWS, 256>>>(inputs, sent, xH, xL);
    long arcTot = (long)NROWS * ARCP, tagTot = (long)NROWS * TAGP;
    run_gemm(xH, xL, Dd, whaH, whaL, ARCP, haF, NROWS, Dd);
    bias_act_split<<<(unsigned)((arcTot + 255) / 256), 256>>>(haF, b_ha, haH, haL, ARCP, ARCc, arcTot, 1);
    run_gemm(xH, xL, Dd, wdaH, wdaL, ARCP, daF, NROWS, Dd);
    bias_act_split<<<(unsigned)((arcTot + 255) / 256), 256>>>(daF, b_da, daH, daL, ARCP, ARCc, arcTot, 1);
    run_gemm(xH, xL, Dd, whtH, whtL, TAGP, htF, NROWS, Dd);
    bias_act_split<<<(unsigned)((tagTot + 255) / 256), 256>>>(htF, b_ht, htH, htL, TAGP, TAGc, tagTot, 1);
    run_gemm(xH, xL, Dd, wdtH, wdtL, TAGP, dtF, NROWS, Dd);
    bias_act_split<<<(unsigned)((tagTot + 255) / 256), 256>>>(dtF, b_dt, dtH, dtL, TAGP, TAGc, tagTot, 1);

    dim3 bilgrid((SPc + 63) / 64, (SPc + 63) / 64, Bb);
    int smgrid = (NROWS + 7) / 8;

    for (int k = 0; k < 2; k++) {
        run_gemm(haH, haL, ARCP, bilH + (size_t)k * 512 * 512, bilL + (size_t)k * 512 * 512, ARCP, t1F, NROWS, ARCP);
        bias_act_split<<<(unsigned)((arcTot + 255) / 256), 256>>>(
            t1F, bilW + (size_t)k * 501 * 501 + (size_t)500 * 501, t1H, t1L, ARCP, 501, arcTot, 0);
        bil_nt_bf16x3<<<bilgrid, 256>>>(t1H, t1L, t1F, daH, daL, bilb, k, lg);
        smax_topk<<<smgrid, 256>>>(lg);

        // arc streams
        run_gemm(arcH, arcL, ARCP, c1aH, c1aL, ARCP, xw, 2 * NROWS, ARCP);
        gcn_agg_split<<<2 * NROWS, 128>>>(xw, c1ab, nullptr, hH, hL, ARCP, ARCc, 1);
        run_gemm(hH, hL, ARCP, c2aH, c2aL, ARCP, xw, 2 * NROWS, ARCP);
        gcn_agg_split<<<2 * NROWS, 128>>>(xw, c2ab, nullptr, arcH, arcL, ARCP, ARCc, 0);
        // tag streams
        run_gemm(tagH, tagL, TAGP, c1rH, c1rL, TAGP, xw, 2 * NROWS, TAGP);
        gcn_agg_split<<<2 * NROWS, 128>>>(xw, c1rb, nullptr, hH, hL, TAGP, TAGc, 1);
        run_gemm(hH, hL, TAGP, c2rH, c2rL, TAGP, xw, 2 * NROWS, TAGP);
        gcn_agg_split<<<2 * NROWS, 128>>>(xw, c2rb, tagF, tagH, tagL, TAGP, TAGc, 0);
    }

    // final bilinear -> d_out
    run_gemm(haH, haL, ARCP, bilH + (size_t)2 * 512 * 512, bilL + (size_t)2 * 512 * 512, ARCP, t1F, NROWS, ARCP);
    bias_act_split<<<(unsigned)((arcTot + 255) / 256), 256>>>(
        t1F, bilW + (size_t)2 * 501 * 501 + (size_t)500 * 501, t1H, t1L, ARCP, 501, arcTot, 0);
    bil_nt_bf16x3<<<bilgrid, 256>>>(t1H, t1L, t1F, daH, daL, bilb, 2, out);

    // append head_tag, dep_tag
    long arcN = (long)Bb * SPc * SPc;
    long tagN = (long)NROWS * TAGc;
    copy_strided<<<(unsigned)((tagN + 255) / 256), 256>>>(htF, out + arcN, TAGP, TAGc, NROWS);
    copy_strided<<<(unsigned)((tagN + 255) / 256), 256>>>(dtF, out + arcN + tagN, TAGP, TAGc, NROWS);
}

// round 5
// speedup vs baseline: 2.8997x; 1.0805x over previous
#include <cuda_runtime.h>
#include <cuda_bf16.h>
#include <math.h>
#include <mma.h>
using namespace nvcuda;

// ---------------- problem constants ----------------
static const int Bb   = 128;
static const int Ss   = 256;
static const int Dd   = 768;
static const int SPc  = 257;
static const int NROWS = Bb * SPc;           // 32896 = 257*128
static const int ARCc = 500;
static const int TAGc = 100;
static const int TOPKc = 8;
static const int ARCP = 512;
static const int TAGP = 128;

// GEMM tiling
static const int ASTR = 40;                   // A smem row stride (elems)
static const int BSTR = 136;                  // B smem row stride (elems)
static const int APLANE = 128 * ASTR;         // elems per A plane per stage
static const int BPLANE = 32 * BSTR;          // elems per B plane per stage
static const int STAGE_ELEMS = 2 * APLANE + 2 * BPLANE;   // 18944
static const int NSTAGE = 3;
static const int GEMM_SMEM = STAGE_ELEMS * NSTAGE * 2;    // 113664 B

// ---------------- fp32 scratch ----------------
__device__ float g_arc [2 * NROWS * ARCP];
__device__ float g_tag [2 * NROWS * TAGP];
__device__ float g_t1  [NROWS * ARCP];
__device__ float g_lg  [Bb * SPc * SPc];
__device__ float g_xw  [2 * NROWS * ARCP];
__device__ float g_vals[NROWS * TOPKc];
__device__ int   g_idx [NROWS * TOPKc];
__device__ float g_dinv[NROWS];

// ---------------- bf16 hi/lo planes ----------------
__device__ __nv_bfloat16 g_xH[NROWS * Dd],        g_xL[NROWS * Dd];
__device__ __nv_bfloat16 g_arcH[2 * NROWS * ARCP], g_arcL[2 * NROWS * ARCP];
__device__ __nv_bfloat16 g_tagH[2 * NROWS * TAGP], g_tagL[2 * NROWS * TAGP];
__device__ __nv_bfloat16 g_t1H[NROWS * ARCP],      g_t1L[NROWS * ARCP];
__device__ __nv_bfloat16 g_hH[2 * NROWS * ARCP],   g_hL[2 * NROWS * ARCP];
__device__ __nv_bfloat16 g_whaH[768 * 512], g_whaL[768 * 512];
__device__ __nv_bfloat16 g_wdaH[768 * 512], g_wdaL[768 * 512];
__device__ __nv_bfloat16 g_whtH[768 * 128], g_whtL[768 * 128];
__device__ __nv_bfloat16 g_wdtH[768 * 128], g_wdtL[768 * 128];
__device__ __nv_bfloat16 g_bilH[3 * 512 * 512], g_bilL[3 * 512 * 512];
__device__ __nv_bfloat16 g_c1aH[512 * 512], g_c1aL[512 * 512];
__device__ __nv_bfloat16 g_c2aH[512 * 512], g_c2aL[512 * 512];
__device__ __nv_bfloat16 g_c1rH[128 * 128], g_c1rL[128 * 128];
__device__ __nv_bfloat16 g_c2rH[128 * 128], g_c2rL[128 * 128];

__device__ __forceinline__ void splitbf(float v, __nv_bfloat16& h, __nv_bfloat16& l) {
    h = __float2bfloat16(v);
    l = __float2bfloat16(v - __bfloat162float(h));
}

// ---------------- small kernels ----------------

__global__ void pad_split_w(const float* __restrict__ W, int Wr, int Wc, int ldw,
                            __nv_bfloat16* __restrict__ hi, __nv_bfloat16* __restrict__ lo,
                            int Kp, int Np) {
    int i = blockIdx.x * blockDim.x + threadIdx.x;
    if (i >= Kp * Np) return;
    int r = i / Np, c = i % Np;
    float v = (r < Wr && c < Wc) ? W[(size_t)r * ldw + c] : 0.f;
    splitbf(v, hi[i], lo[i]);
}

__global__ void build_x_split(const float* __restrict__ inp, const float* __restrict__ sent,
                              __nv_bfloat16* __restrict__ xh, __nv_bfloat16* __restrict__ xl) {
    int n = blockIdx.x;
    int b = n / SPc, r = n % SPc;
    const float* src = (r == 0) ? sent : (inp + ((size_t)b * Ss + (r - 1)) * Dd);
    for (int f = threadIdx.x; f < Dd; f += blockDim.x) {
        splitbf(src[f], xh[(size_t)n * Dd + f], xl[(size_t)n * Dd + f]);
    }
}

__global__ void bias_act_split(float* __restrict__ C, const float* __restrict__ bias,
                               __nv_bfloat16* __restrict__ hi, __nv_bfloat16* __restrict__ lo,
                               int ld, int valid, long total, int act) {
    long i = (long)blockIdx.x * blockDim.x + threadIdx.x;
    if (i >= total) return;
    int n = (int)(i % ld);
    float v = C[i];
    if (n < valid) v += bias[n];
    if (act) v = (v > 0.f) ? v : expm1f(v);
    C[i] = v;
    splitbf(v, hi[i], lo[i]);
}

// ---------------- main GEMM: 3xBF16, 128x128x32 tile, 3-stage cp.async ----------------

__device__ __forceinline__ void cp16(void* dst, const void* src) {
    unsigned d = (unsigned)__cvta_generic_to_shared(dst);
    asm volatile("cp.async.cg.shared.global [%0], [%1], 16;" :: "r"(d), "l"(src));
}

__global__ void __launch_bounds__(256, 1)
gemm_bf16x3(const __nv_bfloat16* __restrict__ Ah, const __nv_bfloat16* __restrict__ Al, int lda,
            const __nv_bfloat16* __restrict__ Bh, const __nv_bfloat16* __restrict__ Bl, int ldb,
            float* __restrict__ C, int ldc, int Kpad) {
    extern __shared__ __nv_bfloat16 sm[];
    int tid = threadIdx.x;
    int warp = tid >> 5;
    int wm = warp & 3;           // 4 warps x 32 rows
    int wn = warp >> 2;          // 2 warps x 64 cols
    int m0 = blockIdx.y * 128, n0 = blockIdx.x * 128;

    wmma::fragment<wmma::accumulator, 16, 16, 16, float> acc[2][4];
#pragma unroll
    for (int i = 0; i < 2; i++)
#pragma unroll
        for (int j = 0; j < 4; j++) wmma::fill_fragment(acc[i][j], 0.f);

    int nk = Kpad >> 5;

    // stage loader
    auto load_stage = [&](int st, int k0) {
        __nv_bfloat16* a0 = sm + st * STAGE_ELEMS;
        __nv_bfloat16* a1 = a0 + APLANE;
        __nv_bfloat16* b0 = a0 + 2 * APLANE;
        __nv_bfloat16* b1 = b0 + BPLANE;
#pragma unroll
        for (int l = 0; l < 2; l++) {
            int id = tid + l * 256;
            int r = id >> 2, c8 = (id & 3) * 8;
            cp16(a0 + r * ASTR + c8, Ah + (size_t)(m0 + r) * lda + k0 + c8);
            cp16(a1 + r * ASTR + c8, Al + (size_t)(m0 + r) * lda + k0 + c8);
        }
#pragma unroll
        for (int l = 0; l < 2; l++) {
            int id = tid + l * 256;
            int r = id >> 4, c8 = (id & 15) * 8;
            cp16(b0 + r * BSTR + c8, Bh + (size_t)(k0 + r) * ldb + n0 + c8);
            cp16(b1 + r * BSTR + c8, Bl + (size_t)(k0 + r) * ldb + n0 + c8);
        }
        asm volatile("cp.async.commit_group;");
    };

    load_stage(0, 0);
    if (nk > 1) load_stage(1, 32);

    for (int kt = 0; kt < nk; kt++) {
        if (kt + 1 < nk) asm volatile("cp.async.wait_group 1;");
        else             asm volatile("cp.async.wait_group 0;");
        __syncthreads();
        if (kt + 2 < nk) load_stage((kt + 2) % NSTAGE, (kt + 2) << 5);

        int st = kt % NSTAGE;
        const __nv_bfloat16* a0 = sm + st * STAGE_ELEMS;
        const __nv_bfloat16* a1 = a0 + APLANE;
        const __nv_bfloat16* b0 = a0 + 2 * APLANE;
        const __nv_bfloat16* b1 = b0 + BPLANE;
#pragma unroll
        for (int ks = 0; ks < 2; ks++) {
            wmma::fragment<wmma::matrix_a, 16, 16, 16, __nv_bfloat16, wmma::row_major> fah[2], fal[2];
            wmma::fragment<wmma::matrix_b, 16, 16, 16, __nv_bfloat16, wmma::row_major> fbh[4], fbl[4];
#pragma unroll
            for (int i = 0; i < 2; i++) {
                wmma::load_matrix_sync(fah[i], a0 + (wm * 32 + i * 16) * ASTR + ks * 16, ASTR);
                wmma::load_matrix_sync(fal[i], a1 + (wm * 32 + i * 16) * ASTR + ks * 16, ASTR);
            }
#pragma unroll
            for (int j = 0; j < 4; j++) {
                wmma::load_matrix_sync(fbh[j], b0 + (ks * 16) * BSTR + wn * 64 + j * 16, BSTR);
                wmma::load_matrix_sync(fbl[j], b1 + (ks * 16) * BSTR + wn * 64 + j * 16, BSTR);
            }
#pragma unroll
            for (int i = 0; i < 2; i++)
#pragma unroll
                for (int j = 0; j < 4; j++) {
                    wmma::mma_sync(acc[i][j], fal[i], fbh[j], acc[i][j]);
                    wmma::mma_sync(acc[i][j], fah[i], fbl[j], acc[i][j]);
                    wmma::mma_sync(acc[i][j], fah[i], fbh[j], acc[i][j]);
                }
        }
        __syncthreads();
    }
#pragma unroll
    for (int i = 0; i < 2; i++)
#pragma unroll
        for (int j = 0; j < 4; j++)
            wmma::store_matrix_sync(C + (size_t)(m0 + wm * 32 + i * 16) * ldc + n0 + wn * 64 + j * 16,
                                    acc[i][j], ldc, wmma::mem_row_major);
}

// ---------------- batched bilinear NT (3xBF16, col-major B frags) ----------------
__global__ void bil_nt_bf16x3(const __nv_bfloat16* __restrict__ t1h, const __nv_bfloat16* __restrict__ t1l,
                              const float* __restrict__ t1f,
                              const __nv_bfloat16* __restrict__ dah, const __nv_bfloat16* __restrict__ dal,
                              const float* __restrict__ bilb, int kidx, float* __restrict__ Cout) {
    __shared__ __nv_bfloat16 As[2][64][40];
    __shared__ __nv_bfloat16 Bs[2][64][40];
    __shared__ float Cs[64][68];
    int bz = blockIdx.z;
    int i0 = blockIdx.y * 64, j0 = blockIdx.x * 64;
    int tid = threadIdx.x, warp = tid >> 5;
    int wm = warp & 3, wn = warp >> 2;
    size_t aoff = (size_t)bz * SPc * ARCP;

    wmma::fragment<wmma::accumulator, 16, 16, 16, float> acc[2];
    wmma::fill_fragment(acc[0], 0.f);
    wmma::fill_fragment(acc[1], 0.f);

    int r = tid >> 2, co = (tid & 3) * 8;
    int gi = i0 + r, gj = j0 + r;

    for (int k0 = 0; k0 < ARCP; k0 += 32) {
        uint4 z = make_uint4(0, 0, 0, 0);
        uint4 vh = (gi < SPc) ? *(const uint4*)(t1h + aoff + (size_t)gi * ARCP + k0 + co) : z;
        uint4 vl = (gi < SPc) ? *(const uint4*)(t1l + aoff + (size_t)gi * ARCP + k0 + co) : z;
        uint4 wh = (gj < SPc) ? *(const uint4*)(dah + aoff + (size_t)gj * ARCP + k0 + co) : z;
        uint4 wl = (gj < SPc) ? *(const uint4*)(dal + aoff + (size_t)gj * ARCP + k0 + co) : z;
        *(uint4*)&As[0][r][co] = vh;
        *(uint4*)&As[1][r][co] = vl;
        *(uint4*)&Bs[0][r][co] = wh;
        *(uint4*)&Bs[1][r][co] = wl;
        __syncthreads();
#pragma unroll
        for (int ks = 0; ks < 2; ks++) {
            wmma::fragment<wmma::matrix_a, 16, 16, 16, __nv_bfloat16, wmma::row_major> fah, fal;
            wmma::fragment<wmma::matrix_b, 16, 16, 16, __nv_bfloat16, wmma::col_major> fbh[2], fbl[2];
            wmma::load_matrix_sync(fah, &As[0][wm * 16][ks * 16], 40);
            wmma::load_matrix_sync(fal, &As[1][wm * 16][ks * 16], 40);
#pragma unroll
            for (int j = 0; j < 2; j++) {
                wmma::load_matrix_sync(fbh[j], &Bs[0][wn * 32 + j * 16][ks * 16], 40);
                wmma::load_matrix_sync(fbl[j], &Bs[1][wn * 32 + j * 16][ks * 16], 40);
            }
#pragma unroll
            for (int j = 0; j < 2; j++) {
                wmma::mma_sync(acc[j], fal, fbh[j], acc[j]);
                wmma::mma_sync(acc[j], fah, fbl[j], acc[j]);
                wmma::mma_sync(acc[j], fah, fbh[j], acc[j]);
            }
        }
        __syncthreads();
    }
    wmma::store_matrix_sync(&Cs[wm * 16][wn * 32], acc[0], 68, wmma::mem_row_major);
    wmma::store_matrix_sync(&Cs[wm * 16][wn * 32 + 16], acc[1], 68, wmma::mem_row_major);
    __syncthreads();
    float bb = bilb[kidx];
#pragma unroll
    for (int l = 0; l < 16; l++) {
        int id = tid + l * 256;
        int rr = id >> 6, cc = id & 63;
        int oi = i0 + rr, oj = j0 + cc;
        if (oi < SPc && oj < SPc)
            Cout[((size_t)bz * SPc + oi) * SPc + oj] =
                Cs[rr][cc] + t1f[aoff + (size_t)oi * ARCP + ARCc] + bb;
    }
}

// ---------------- fused softmax + top-8 + dinv ----------------
__global__ void smax_topk(const float* __restrict__ lg) {
    int row = blockIdx.x * 8 + (threadIdx.x >> 5);
    int lane = threadIdx.x & 31;
    if (row >= NROWS) return;
    const float* p = lg + (size_t)row * SPc;
    float v[9];
    float mx = -INFINITY;
#pragma unroll
    for (int t = 0; t < 9; t++) {
        int c = lane + 32 * t;
        v[t] = (c < SPc) ? p[c] : -INFINITY;
        mx = fmaxf(mx, v[t]);
    }
#pragma unroll
    for (int off = 16; off > 0; off >>= 1) mx = fmaxf(mx, __shfl_xor_sync(0xffffffffu, mx, off));
    float s = 0.f;
#pragma unroll
    for (int t = 0; t < 9; t++) {
        int c = lane + 32 * t;
        if (c < SPc) { v[t] = expf(v[t] - mx); s += v[t]; } else v[t] = -INFINITY;
    }
#pragma unroll
    for (int off = 16; off > 0; off >>= 1) s += __shfl_xor_sync(0xffffffffu, s, off);
    float inv = 1.f / s;
#pragma unroll
    for (int t = 0; t < 9; t++) {
        int c = lane + 32 * t;
        if (c < SPc) v[t] *= inv;
    }
    float acc8 = 0.f;
    for (int it = 0; it < TOPKc; it++) {
        float bv = -INFINITY; int bi = 0x7fffffff;
#pragma unroll
        for (int t = 0; t < 9; t++) {
            int c = lane + 32 * t;
            if (v[t] > bv || (v[t] == bv && c < bi)) { bv = v[t]; bi = c; }
        }
#pragma unroll
        for (int off = 16; off > 0; off >>= 1) {
            float ov = __shfl_down_sync(0xffffffffu, bv, off);
            int oi   = __shfl_down_sync(0xffffffffu, bi, off);
            if (ov > bv || (ov == bv && oi < bi)) { bv = ov; bi = oi; }
        }
        bv = __shfl_sync(0xffffffffu, bv, 0);
        bi = __shfl_sync(0xffffffffu, bi, 0);
        if (lane == 0) { g_vals[(size_t)row * TOPKc + it] = bv; g_idx[(size_t)row * TOPKc + it] = bi; }
        acc8 += bv;
        if (lane == (bi & 31)) v[bi >> 5] = -INFINITY;
    }
    if (lane == 0) g_dinv[row] = rsqrtf(1.f + acc8);
}

// ---------------- GCN aggregate + ELU + split ----------------
__global__ void gcn_agg_split(const float* __restrict__ xw, const float* __restrict__ bias,
                              float* __restrict__ outf,
                              __nv_bfloat16* __restrict__ outh, __nv_bfloat16* __restrict__ outl,
                              int Fp, int Fv, int act) {
    int gid = blockIdx.x;
    int i = gid % NROWS;
    int stream = gid / NROWS;
    int b = i / SPc;
    __shared__ float cf[TOPKc];
    __shared__ int   ss[TOPKc];
    float di = g_dinv[i];
    if (threadIdx.x < TOPKc) {
        int k = threadIdx.x;
        int srow = b * SPc + g_idx[(size_t)i * TOPKc + k];
        ss[k] = stream * NROWS + srow;
        cf[k] = di * g_vals[(size_t)i * TOPKc + k] * g_dinv[srow];
    }
    __syncthreads();
    float selfc = di * di;
    const float* xwi = xw + (size_t)gid * Fp;
    for (int f = threadIdx.x; f < Fp; f += blockDim.x) {
        float acc = selfc * xwi[f];
#pragma unroll
        for (int k = 0; k < TOPKc; k++) acc += cf[k] * xw[(size_t)ss[k] * Fp + f];
        if (f < Fv) acc += bias[f];
        if (act) acc = (acc > 0.f) ? acc : expm1f(acc);
        size_t o = (size_t)gid * Fp + f;
        if (outf) outf[o] = acc;
        splitbf(acc, outh[o], outl[o]);
    }
}

__global__ void copy_strided(const float* __restrict__ src, float* __restrict__ dst,
                             int ld, int valid, int rows) {
    long i = (long)blockIdx.x * blockDim.x + threadIdx.x;
    long total = (long)rows * valid;
    if (i >= total) return;
    int n = (int)(i / valid), f = (int)(i % valid);
    dst[i] = src[(size_t)n * ld + f];
}

// ---------------- host ----------------
template <typename T>
static T* sym(const void* s) { void* p; cudaGetSymbolAddress(&p, s); return (T*)p; }

static void run_gemm(const __nv_bfloat16* Ah, const __nv_bfloat16* Al, int lda,
                     const __nv_bfloat16* Bh, const __nv_bfloat16* Bl, int Npad,
                     float* C, int M, int Kpad) {
    dim3 grid(Npad / 128, M / 128);
    gemm_bf16x3<<<grid, 256, GEMM_SMEM>>>(Ah, Al, lda, Bh, Bl, Npad, C, Npad, Kpad);
}

extern "C" void kernel_launch(void* const* d_in, const int* in_sizes, int n_in,
                              void* d_out, int out_size) {
    const float* inputs = (const float*)d_in[0];
    const float* sent   = (const float*)d_in[5];
    const float* W_ha = (const float*)d_in[6];  const float* b_ha = (const float*)d_in[7];
    const float* W_da = (const float*)d_in[8];  const float* b_da = (const float*)d_in[9];
    const float* W_ht = (const float*)d_in[10]; const float* b_ht = (const float*)d_in[11];
    const float* W_dt = (const float*)d_in[12]; const float* b_dt = (const float*)d_in[13];
    const float* bilW = (const float*)d_in[14]; const float* bilb = (const float*)d_in[15];
    const float* c1aW = (const float*)d_in[16]; const float* c1ab = (const float*)d_in[17];
    const float* c2aW = (const float*)d_in[18]; const float* c2ab = (const float*)d_in[19];
    const float* c1rW = (const float*)d_in[20]; const float* c1rb = (const float*)d_in[21];
    const float* c2rW = (const float*)d_in[22]; const float* c2rb = (const float*)d_in[23];
    float* out = (float*)d_out;

    cudaFuncSetAttribute(gemm_bf16x3, cudaFuncAttributeMaxDynamicSharedMemorySize, GEMM_SMEM);

    float* arcF = sym<float>(g_arc);
    float* tagF = sym<float>(g_tag);
    float* t1F  = sym<float>(g_t1);
    float* lg   = sym<float>(g_lg);
    float* xw   = sym<float>(g_xw);
    __nv_bfloat16 *xH = sym<__nv_bfloat16>(g_xH), *xL = sym<__nv_bfloat16>(g_xL);
    __nv_bfloat16 *arcH = sym<__nv_bfloat16>(g_arcH), *arcL = sym<__nv_bfloat16>(g_arcL);
    __nv_bfloat16 *tagH = sym<__nv_bfloat16>(g_tagH), *tagL = sym<__nv_bfloat16>(g_tagL);
    __nv_bfloat16 *t1H = sym<__nv_bfloat16>(g_t1H), *t1L = sym<__nv_bfloat16>(g_t1L);
    __nv_bfloat16 *hH = sym<__nv_bfloat16>(g_hH), *hL = sym<__nv_bfloat16>(g_hL);
    __nv_bfloat16 *whaH = sym<__nv_bfloat16>(g_whaH), *whaL = sym<__nv_bfloat16>(g_whaL);
    __nv_bfloat16 *wdaH = sym<__nv_bfloat16>(g_wdaH), *wdaL = sym<__nv_bfloat16>(g_wdaL);
    __nv_bfloat16 *whtH = sym<__nv_bfloat16>(g_whtH), *whtL = sym<__nv_bfloat16>(g_whtL);
    __nv_bfloat16 *wdtH = sym<__nv_bfloat16>(g_wdtH), *wdtL = sym<__nv_bfloat16>(g_wdtL);
    __nv_bfloat16 *bilH = sym<__nv_bfloat16>(g_bilH), *bilL = sym<__nv_bfloat16>(g_bilL);
    __nv_bfloat16 *c1aH = sym<__nv_bfloat16>(g_c1aH), *c1aL = sym<__nv_bfloat16>(g_c1aL);
    __nv_bfloat16 *c2aH = sym<__nv_bfloat16>(g_c2aH), *c2aL = sym<__nv_bfloat16>(g_c2aL);
    __nv_bfloat16 *c1rH = sym<__nv_bfloat16>(g_c1rH), *c1rL = sym<__nv_bfloat16>(g_c1rL);
    __nv_bfloat16 *c2rH = sym<__nv_bfloat16>(g_c2rH), *c2rL = sym<__nv_bfloat16>(g_c2rL);

    float* haF = arcF;
    float* daF = arcF + (size_t)NROWS * ARCP;
    __nv_bfloat16 *haH = arcH, *haL = arcL;
    __nv_bfloat16 *daH = arcH + (size_t)NROWS * ARCP, *daL = arcL + (size_t)NROWS * ARCP;
    float* htF = tagF;
    float* dtF = tagF + (size_t)NROWS * TAGP;
    __nv_bfloat16 *htH = tagH, *htL = tagL;
    __nv_bfloat16 *dtH = tagH + (size_t)NROWS * TAGP, *dtL = tagL + (size_t)NROWS * TAGP;

    // --- weight pad + split ---
    pad_split_w<<<(768 * 512 + 255) / 256, 256>>>(W_ha, 768, 500, 500, whaH, whaL, 768, 512);
    pad_split_w<<<(768 * 512 + 255) / 256, 256>>>(W_da, 768, 500, 500, wdaH, wdaL, 768, 512);
    pad_split_w<<<(768 * 128 + 255) / 256, 256>>>(W_ht, 768, 100, 100, whtH, whtL, 768, 128);
    pad_split_w<<<(768 * 128 + 255) / 256, 256>>>(W_dt, 768, 100, 100, wdtH, wdtL, 768, 128);
    for (int k = 0; k < 3; k++)
        pad_split_w<<<(512 * 512 + 255) / 256, 256>>>(bilW + (size_t)k * 501 * 501, 500, 501, 501,
                                                      bilH + (size_t)k * 512 * 512, bilL + (size_t)k * 512 * 512, 512, 512);
    pad_split_w<<<(512 * 512 + 255) / 256, 256>>>(c1aW, 500, 500, 500, c1aH, c1aL, 512, 512);
    pad_split_w<<<(512 * 512 + 255) / 256, 256>>>(c2aW, 500, 500, 500, c2aH, c2aL, 512, 512);
    pad_split_w<<<(128 * 128 + 255) / 256, 256>>>(c1rW, 100, 100, 100, c1rH, c1rL, 128, 128);
    pad_split_w<<<(128 * 128 + 255) / 256, 256>>>(c2rW, 100, 100, 100, c2rH, c2rL, 128, 128);

    // --- x + projections ---
    build_x_split<<<NROWS, 256>>>(inputs, sent, xH, xL);
    long arcTot = (long)NROWS * ARCP, tagTot = (long)NROWS * TAGP;
    run_gemm(xH, xL, Dd, whaH, whaL, ARCP, haF, NROWS, Dd);
    bias_act_split<<<(unsigned)((arcTot + 255) / 256), 256>>>(haF, b_ha, haH, haL, ARCP, ARCc, arcTot, 1);
    run_gemm(xH, xL, Dd, wdaH, wdaL, ARCP, daF, NROWS, Dd);
    bias_act_split<<<(unsigned)((arcTot + 255) / 256), 256>>>(daF, b_da, daH, daL, ARCP, ARCc, arcTot, 1);
    run_gemm(xH, xL, Dd, whtH, whtL, TAGP, htF, NROWS, Dd);
    bias_act_split<<<(unsigned)((tagTot + 255) / 256), 256>>>(htF, b_ht, htH, htL, TAGP, TAGc, tagTot, 1);
    run_gemm(xH, xL, Dd, wdtH, wdtL, TAGP, dtF, NROWS, Dd);
    bias_act_split<<<(unsigned)((tagTot + 255) / 256), 256>>>(dtF, b_dt, dtH, dtL, TAGP, TAGc, tagTot, 1);

    dim3 bilgrid((SPc + 63) / 64, (SPc + 63) / 64, Bb);
    int smgrid = (NROWS + 7) / 8;

    for (int k = 0; k < 2; k++) {
        run_gemm(haH, haL, ARCP, bilH + (size_t)k * 512 * 512, bilL + (size_t)k * 512 * 512, ARCP, t1F, NROWS, ARCP);
        bias_act_split<<<(unsigned)((arcTot + 255) / 256), 256>>>(
            t1F, bilW + (size_t)k * 501 * 501 + (size_t)500 * 501, t1H, t1L, ARCP, 501, arcTot, 0);
        bil_nt_bf16x3<<<bilgrid, 256>>>(t1H, t1L, t1F, daH, daL, bilb, k, lg);
        smax_topk<<<smgrid, 256>>>(lg);

        // arc streams
        run_gemm(arcH, arcL, ARCP, c1aH, c1aL, ARCP, xw, 2 * NROWS, ARCP);
        gcn_agg_split<<<2 * NROWS, 128>>>(xw, c1ab, nullptr, hH, hL, ARCP, ARCc, 1);
        run_gemm(hH, hL, ARCP, c2aH, c2aL, ARCP, xw, 2 * NROWS, ARCP);
        gcn_agg_split<<<2 * NROWS, 128>>>(xw, c2ab, nullptr, arcH, arcL, ARCP, ARCc, 0);
        // tag streams
        run_gemm(tagH, tagL, TAGP, c1rH, c1rL, TAGP, xw, 2 * NROWS, TAGP);
        gcn_agg_split<<<2 * NROWS, 128>>>(xw, c1rb, nullptr, hH, hL, TAGP, TAGc, 1);
        run_gemm(hH, hL, TAGP, c2rH, c2rL, TAGP, xw, 2 * NROWS, TAGP);
        gcn_agg_split<<<2 * NROWS, 128>>>(xw, c2rb, tagF, tagH, tagL, TAGP, TAGc, 0);
    }

    // final bilinear -> d_out
    run_gemm(haH, haL, ARCP, bilH + (size_t)2 * 512 * 512, bilL + (size_t)2 * 512 * 512, ARCP, t1F, NROWS, ARCP);
    bias_act_split<<<(unsigned)((arcTot + 255) / 256), 256>>>(
        t1F, bilW + (size_t)2 * 501 * 501 + (size_t)500 * 501, t1H, t1L, ARCP, 501, arcTot, 0);
    bil_nt_bf16x3<<<bilgrid, 256>>>(t1H, t1L, t1F, daH, daL, bilb, 2, out);

    // append head_tag, dep_tag
    long arcN = (long)Bb * SPc * SPc;
    long tagN = (long)NROWS * TAGc;
    copy_strided<<<(unsigned)((tagN + 255) / 256), 256>>>(htF, out + arcN, TAGP, TAGc, NROWS);
    copy_strided<<<(unsigned)((tagN + 255) / 256), 256>>>(dtF, out + arcN + tagN, TAGP, TAGc, NROWS);
}

// round 7
// speedup vs baseline: 3.5679x; 1.2305x over previous
#include <cuda_runtime.h>
#include <cuda_bf16.h>
#include <math.h>
#include <mma.h>
#include <stdint.h>
using namespace nvcuda;

// ---------------- problem constants ----------------
static const int Bb   = 128;
static const int Ss   = 256;
static const int Dd   = 768;
static const int SPc  = 257;
static const int NROWS = Bb * SPc;           // 32896 = 257*128
static const int ARCc = 500;
static const int TAGc = 100;
static const int TOPKc = 8;
static const int ARCP = 512;
static const int TAGP = 128;

// GEMM tiling: 128x128 CTA tile, 4 warps (64x64 each), k-chunk 32, 3-stage
static const int ASTR = 40;                   // A smem row stride (elems)
static const int BSTR = 136;                  // B smem row stride (elems)
static const int APL  = 128 * ASTR;           // elems per A plane
static const int BPL  = 32 * BSTR;            // elems per B plane
static const int STG  = 2 * APL + 2 * BPL;    // 18944 elems / stage
static const int NST  = 3;
static const int GSMEM = NST * STG * 2;       // 113664 B  (2 CTAs/SM -> 222KB)

// ---------------- fp32 scratch ----------------
__device__ float g_tag [2 * NROWS * TAGP];
__device__ float g_t1  [NROWS * ARCP];
__device__ float g_lg  [Bb * SPc * SPc];
__device__ float g_xw  [2 * NROWS * ARCP];
__device__ float g_vals[NROWS * TOPKc];
__device__ int   g_idx [NROWS * TOPKc];
__device__ float g_dinv[NROWS];

// ---------------- bf16 hi/lo planes ----------------
__device__ __align__(16) __nv_bfloat16 g_xH[NROWS * Dd],         g_xL[NROWS * Dd];
__device__ __align__(16) __nv_bfloat16 g_arcH[2 * NROWS * ARCP], g_arcL[2 * NROWS * ARCP];
__device__ __align__(16) __nv_bfloat16 g_tagH[2 * NROWS * TAGP], g_tagL[2 * NROWS * TAGP];
__device__ __align__(16) __nv_bfloat16 g_t1H[NROWS * ARCP],      g_t1L[NROWS * ARCP];
__device__ __align__(16) __nv_bfloat16 g_hH[2 * NROWS * ARCP],   g_hL[2 * NROWS * ARCP];
// weights [Kpad, Npad] row-major, padded, split
__device__ __align__(16) __nv_bfloat16 g_whaH[768 * 512], g_whaL[768 * 512];
__device__ __align__(16) __nv_bfloat16 g_wdaH[768 * 512], g_wdaL[768 * 512];
__device__ __align__(16) __nv_bfloat16 g_whtH[768 * 128], g_whtL[768 * 128];
__device__ __align__(16) __nv_bfloat16 g_wdtH[768 * 128], g_wdtL[768 * 128];
__device__ __align__(16) __nv_bfloat16 g_bilH[3 * 512 * 512], g_bilL[3 * 512 * 512];
__device__ __align__(16) __nv_bfloat16 g_c1aH[512 * 512], g_c1aL[512 * 512];
__device__ __align__(16) __nv_bfloat16 g_c2aH[512 * 512], g_c2aL[512 * 512];
__device__ __align__(16) __nv_bfloat16 g_c1rH[128 * 128], g_c1rL[128 * 128];
__device__ __align__(16) __nv_bfloat16 g_c2rH[128 * 128], g_c2rL[128 * 128];

__device__ __forceinline__ void splitbf(float v, __nv_bfloat16& h, __nv_bfloat16& l) {
    h = __float2bfloat16(v);
    l = __float2bfloat16(v - __bfloat162float(h));
}
__device__ __forceinline__ void cp16(void* dst, const void* src) {
    unsigned d = (unsigned)__cvta_generic_to_shared(dst);
    asm volatile("cp.async.cg.shared.global [%0], [%1], 16;" :: "r"(d), "l"(src));
}

// ---------------- small kernels ----------------

__global__ void pad_split_w(const float* __restrict__ W, int Wr, int Wc, int ldw,
                            __nv_bfloat16* __restrict__ hi, __nv_bfloat16* __restrict__ lo,
                            int Kp, int Np) {
    int i = blockIdx.x * blockDim.x + threadIdx.x;
    if (i >= Kp * Np) return;
    int r = i / Np, c = i % Np;
    float v = (r < Wr && c < Wc) ? W[(size_t)r * ldw + c] : 0.f;
    splitbf(v, hi[i], lo[i]);
}

__global__ void build_x_split(const float* __restrict__ inp, const float* __restrict__ sent,
                              __nv_bfloat16* __restrict__ xh, __nv_bfloat16* __restrict__ xl) {
    int n = blockIdx.x;
    int b = n / SPc, r = n % SPc;
    const float* src = (r == 0) ? sent : (inp + ((size_t)b * Ss + (r - 1)) * Dd);
    for (int f = threadIdx.x; f < Dd; f += blockDim.x)
        splitbf(src[f], xh[(size_t)n * Dd + f], xl[(size_t)n * Dd + f]);
}

// ---------------- main GEMM: 3xBF16, 128x128 tile, 4 warps 64x64, fused epilogue ----------------
__global__ void __launch_bounds__(128, 2)
gemm_bf16x3(const __nv_bfloat16* __restrict__ Ah, const __nv_bfloat16* __restrict__ Al, int lda,
            const __nv_bfloat16* __restrict__ Bh, const __nv_bfloat16* __restrict__ Bl, int ldb,
            float* __restrict__ Cf, int ldc,
            __nv_bfloat16* __restrict__ oH, __nv_bfloat16* __restrict__ oL,
            const float* __restrict__ bias, int validN, int act, int Kpad) {
    extern __shared__ __nv_bfloat16 sm[];
    int tid = threadIdx.x, warp = tid >> 5;
    int wm = warp & 1, wn = warp >> 1;            // 2x2 warp grid, 64x64 each
    int m0 = blockIdx.y << 7, n0 = blockIdx.x << 7;

    wmma::fragment<wmma::accumulator, 16, 16, 16, float> acc[4][4];
#pragma unroll
    for (int i = 0; i < 4; i++)
#pragma unroll
        for (int j = 0; j < 4; j++) wmma::fill_fragment(acc[i][j], 0.f);

    int nk = Kpad >> 5;

    auto load_stage = [&](int st, int k0) {
        __nv_bfloat16* a0 = sm + st * STG;
        __nv_bfloat16* a1 = a0 + APL;
        __nv_bfloat16* b0 = a1 + APL;
        __nv_bfloat16* b1 = b0 + BPL;
#pragma unroll
        for (int l = 0; l < 4; l++) {
            int id = tid + l * 128;
            int r = id >> 2, c = (id & 3) * 8;
            cp16(a0 + r * ASTR + c, Ah + (size_t)(m0 + r) * lda + k0 + c);
            cp16(a1 + r * ASTR + c, Al + (size_t)(m0 + r) * lda + k0 + c);
        }
#pragma unroll
        for (int l = 0; l < 4; l++) {
            int id = tid + l * 128;
            int r = id >> 4, c = (id & 15) * 8;
            cp16(b0 + r * BSTR + c, Bh + (size_t)(k0 + r) * ldb + n0 + c);
            cp16(b1 + r * BSTR + c, Bl + (size_t)(k0 + r) * ldb + n0 + c);
        }
        asm volatile("cp.async.commit_group;");
    };

    load_stage(0, 0);
    load_stage(1, 32);

    for (int kt = 0; kt < nk; kt++) {
        if (kt + 1 < nk) asm volatile("cp.async.wait_group 1;");
        else             asm volatile("cp.async.wait_group 0;");
        __syncthreads();
        if (kt + 2 < nk) load_stage((kt + 2) % NST, (kt + 2) << 5);

        int st = kt % NST;
        const __nv_bfloat16* a0 = sm + st * STG;
        const __nv_bfloat16* a1 = a0 + APL;
        const __nv_bfloat16* b0 = a1 + APL;
        const __nv_bfloat16* b1 = b0 + BPL;
#pragma unroll
        for (int ks = 0; ks < 2; ks++) {
            wmma::fragment<wmma::matrix_a, 16, 16, 16, __nv_bfloat16, wmma::row_major> fah[4], fal[4];
            wmma::fragment<wmma::matrix_b, 16, 16, 16, __nv_bfloat16, wmma::row_major> fbh[4], fbl[4];
#pragma unroll
            for (int i = 0; i < 4; i++) {
                wmma::load_matrix_sync(fah[i], a0 + (wm * 64 + i * 16) * ASTR + ks * 16, ASTR);
                wmma::load_matrix_sync(fal[i], a1 + (wm * 64 + i * 16) * ASTR + ks * 16, ASTR);
            }
#pragma unroll
            for (int j = 0; j < 4; j++) {
                wmma::load_matrix_sync(fbh[j], b0 + (ks * 16) * BSTR + wn * 64 + j * 16, BSTR);
                wmma::load_matrix_sync(fbl[j], b1 + (ks * 16) * BSTR + wn * 64 + j * 16, BSTR);
            }
#pragma unroll
            for (int i = 0; i < 4; i++)
#pragma unroll
                for (int j = 0; j < 4; j++) {
                    wmma::mma_sync(acc[i][j], fal[i], fbh[j], acc[i][j]);
                    wmma::mma_sync(acc[i][j], fah[i], fbl[j], acc[i][j]);
                    wmma::mma_sync(acc[i][j], fah[i], fbh[j], acc[i][j]);
                }
        }
        __syncthreads();
    }

    // fused epilogue: frags -> smem -> bias/act/split -> global
    float* Cs = (float*)sm;
#pragma unroll
    for (int i = 0; i < 4; i++)
#pragma unroll
        for (int j = 0; j < 4; j++)
            wmma::store_matrix_sync(Cs + (wm * 64 + i * 16) * 132 + wn * 64 + j * 16,
                                    acc[i][j], 132, wmma::mem_row_major);
    __syncthreads();
    {
        int c = tid;
        int gn = n0 + c;
        float bb = (bias && gn < validN) ? bias[gn] : 0.f;
#pragma unroll 8
        for (int r = 0; r < 128; r++) {
            float v = Cs[r * 132 + c] + bb;
            if (act) v = (v > 0.f) ? v : expm1f(v);
            size_t o = (size_t)(m0 + r) * ldc + gn;
            if (Cf) Cf[o] = v;
            if (oH) { __nv_bfloat16 h, l2; splitbf(v, h, l2); oH[o] = h; oL[o] = l2; }
        }
    }
}

// ---------------- batched bilinear NT (3xBF16 WMMA) ----------------
__global__ void bil_nt_bf16x3(const __nv_bfloat16* __restrict__ t1h, const __nv_bfloat16* __restrict__ t1l,
                              const float* __restrict__ t1f,
                              const __nv_bfloat16* __restrict__ dah, const __nv_bfloat16* __restrict__ dal,
                              const float* __restrict__ bilb, int kidx, float* __restrict__ Cout) {
    __shared__ __nv_bfloat16 As[2][64][40];
    __shared__ __nv_bfloat16 Bs[2][64][40];
    __shared__ float Cs[64][68];
    int bz = blockIdx.z;
    int i0 = blockIdx.y * 64, j0 = blockIdx.x * 64;
    int tid = threadIdx.x, warp = tid >> 5;
    int wm = warp & 3, wn = warp >> 2;
    size_t aoff = (size_t)bz * SPc * ARCP;

    wmma::fragment<wmma::accumulator, 16, 16, 16, float> acc[2];
    wmma::fill_fragment(acc[0], 0.f);
    wmma::fill_fragment(acc[1], 0.f);

    int r = tid >> 2, co = (tid & 3) * 8;
    int gi = i0 + r, gj = j0 + r;

    for (int k0 = 0; k0 < ARCP; k0 += 32) {
        uint4 z = make_uint4(0, 0, 0, 0);
        uint4 vh = (gi < SPc) ? *(const uint4*)(t1h + aoff + (size_t)gi * ARCP + k0 + co) : z;
        uint4 vl = (gi < SPc) ? *(const uint4*)(t1l + aoff + (size_t)gi * ARCP + k0 + co) : z;
        uint4 wh = (gj < SPc) ? *(const uint4*)(dah + aoff + (size_t)gj * ARCP + k0 + co) : z;
        uint4 wl = (gj < SPc) ? *(const uint4*)(dal + aoff + (size_t)gj * ARCP + k0 + co) : z;
        *(uint4*)&As[0][r][co] = vh;
        *(uint4*)&As[1][r][co] = vl;
        *(uint4*)&Bs[0][r][co] = wh;
        *(uint4*)&Bs[1][r][co] = wl;
        __syncthreads();
#pragma unroll
        for (int ks = 0; ks < 2; ks++) {
            wmma::fragment<wmma::matrix_a, 16, 16, 16, __nv_bfloat16, wmma::row_major> fah, fal;
            wmma::fragment<wmma::matrix_b, 16, 16, 16, __nv_bfloat16, wmma::col_major> fbh[2], fbl[2];
            wmma::load_matrix_sync(fah, &As[0][wm * 16][ks * 16], 40);
            wmma::load_matrix_sync(fal, &As[1][wm * 16][ks * 16], 40);
#pragma unroll
            for (int j = 0; j < 2; j++) {
                wmma::load_matrix_sync(fbh[j], &Bs[0][wn * 32 + j * 16][ks * 16], 40);
                wmma::load_matrix_sync(fbl[j], &Bs[1][wn * 32 + j * 16][ks * 16], 40);
            }
#pragma unroll
            for (int j = 0; j < 2; j++) {
                wmma::mma_sync(acc[j], fal, fbh[j], acc[j]);
                wmma::mma_sync(acc[j], fah, fbl[j], acc[j]);
                wmma::mma_sync(acc[j], fah, fbh[j], acc[j]);
            }
        }
        __syncthreads();
    }
    wmma::store_matrix_sync(&Cs[wm * 16][wn * 32], acc[0], 68, wmma::mem_row_major);
    wmma::store_matrix_sync(&Cs[wm * 16][wn * 32 + 16], acc[1], 68, wmma::mem_row_major);
    __syncthreads();
    float bb = bilb[kidx];
#pragma unroll
    for (int l = 0; l < 16; l++) {
        int id = tid + l * 256;
        int rr = id >> 6, cc = id & 63;
        int oi = i0 + rr, oj = j0 + cc;
        if (oi < SPc && oj < SPc)
            Cout[((size_t)bz * SPc + oi) * SPc + oj] =
                Cs[rr][cc] + t1f[aoff + (size_t)oi * ARCP + ARCc] + bb;
    }
}

// ---------------- fused softmax + top-8 + dinv ----------------
__global__ void smax_topk(const float* __restrict__ lg) {
    int row = blockIdx.x * 8 + (threadIdx.x >> 5);
    int lane = threadIdx.x & 31;
    if (row >= NROWS) return;
    const float* p = lg + (size_t)row * SPc;
    float v[9];
    float mx = -INFINITY;
#pragma unroll
    for (int t = 0; t < 9; t++) {
        int c = lane + 32 * t;
        v[t] = (c < SPc) ? p[c] : -INFINITY;
        mx = fmaxf(mx, v[t]);
    }
#pragma unroll
    for (int off = 16; off > 0; off >>= 1) mx = fmaxf(mx, __shfl_xor_sync(0xffffffffu, mx, off));
    float s = 0.f;
#pragma unroll
    for (int t = 0; t < 9; t++) {
        int c = lane + 32 * t;
        if (c < SPc) { v[t] = expf(v[t] - mx); s += v[t]; } else v[t] = -INFINITY;
    }
#pragma unroll
    for (int off = 16; off > 0; off >>= 1) s += __shfl_xor_sync(0xffffffffu, s, off);
    float inv = 1.f / s;
#pragma unroll
    for (int t = 0; t < 9; t++) {
        int c = lane + 32 * t;
        if (c < SPc) v[t] *= inv;
    }
    float acc8 = 0.f;
    for (int it = 0; it < TOPKc; it++) {
        float bv = -INFINITY; int bi = 0x7fffffff;
#pragma unroll
        for (int t = 0; t < 9; t++) {
            int c = lane + 32 * t;
            if (v[t] > bv || (v[t] == bv && c < bi)) { bv = v[t]; bi = c; }
        }
#pragma unroll
        for (int off = 16; off > 0; off >>= 1) {
            float ov = __shfl_down_sync(0xffffffffu, bv, off);
            int oi   = __shfl_down_sync(0xffffffffu, bi, off);
            if (ov > bv || (ov == bv && oi < bi)) { bv = ov; bi = oi; }
        }
        bv = __shfl_sync(0xffffffffu, bv, 0);
        bi = __shfl_sync(0xffffffffu, bi, 0);
        if (lane == 0) { g_vals[(size_t)row * TOPKc + it] = bv; g_idx[(size_t)row * TOPKc + it] = bi; }
        acc8 += bv;
        if (lane == (bi & 31)) v[bi >> 5] = -INFINITY;
    }
    if (lane == 0) g_dinv[row] = rsqrtf(1.f + acc8);
}

// ---------------- GCN aggregate + ELU + split ----------------
__global__ void gcn_agg_split(const float* __restrict__ xw, const float* __restrict__ bias,
                              float* __restrict__ outf,
                              __nv_bfloat16* __restrict__ outh, __nv_bfloat16* __restrict__ outl,
                              int Fp, int Fv, int act) {
    int gid = blockIdx.x;
    int i = gid % NROWS;
    int stream = gid / NROWS;
    int b = i / SPc;
    __shared__ float cf[TOPKc];
    __shared__ int   ss[TOPKc];
    float di = g_dinv[i];
    if (threadIdx.x < TOPKc) {
        int k = threadIdx.x;
        int srow = b * SPc + g_idx[(size_t)i * TOPKc + k];
        ss[k] = stream * NROWS + srow;
        cf[k] = di * g_vals[(size_t)i * TOPKc + k] * g_dinv[srow];
    }
    __syncthreads();
    float selfc = di * di;
    const float* xwi = xw + (size_t)gid * Fp;
    for (int f = threadIdx.x; f < Fp; f += blockDim.x) {
        float acc = selfc * xwi[f];
#pragma unroll
        for (int k = 0; k < TOPKc; k++) acc += cf[k] * xw[(size_t)ss[k] * Fp + f];
        if (f < Fv) acc += bias[f];
        if (act) acc = (acc > 0.f) ? acc : expm1f(acc);
        size_t o = (size_t)gid * Fp + f;
        if (outf) outf[o] = acc;
        splitbf(acc, outh[o], outl[o]);
    }
}

__global__ void copy_strided(const float* __restrict__ src, float* __restrict__ dst,
                             int ld, int valid, int rows) {
    long i = (long)blockIdx.x * blockDim.x + threadIdx.x;
    long total = (long)rows * valid;
    if (i >= total) return;
    int n = (int)(i / valid), f = (int)(i % valid);
    dst[i] = src[(size_t)n * ld + f];
}

// ---------------- host ----------------
template <typename T>
static T* sym(const void* s) { void* p; cudaGetSymbolAddress(&p, s); return (T*)p; }

static void run_gemm(const __nv_bfloat16* Ah, const __nv_bfloat16* Al, int lda,
                     const __nv_bfloat16* Bh, const __nv_bfloat16* Bl, int Npad,
                     float* Cf, __nv_bfloat16* oH, __nv_bfloat16* oL,
                     const float* bias, int validN, int act,
                     int M, int Kpad) {
    dim3 grid(Npad >> 7, M >> 7);
    gemm_bf16x3<<<grid, 128, GSMEM>>>(Ah, Al, lda, Bh, Bl, Npad, Cf, Npad, oH, oL, bias, validN, act, Kpad);
}

extern "C" void kernel_launch(void* const* d_in, const int* in_sizes, int n_in,
                              void* d_out, int out_size) {
    const float* inputs = (const float*)d_in[0];
    const float* sent   = (const float*)d_in[5];
    const float* W_ha = (const float*)d_in[6];  const float* b_ha = (const float*)d_in[7];
    const float* W_da = (const float*)d_in[8];  const float* b_da = (const float*)d_in[9];
    const float* W_ht = (const float*)d_in[10]; const float* b_ht = (const float*)d_in[11];
    const float* W_dt = (const float*)d_in[12]; const float* b_dt = (const float*)d_in[13];
    const float* bilW = (const float*)d_in[14]; const float* bilb = (const float*)d_in[15];
    const float* c1aW = (const float*)d_in[16]; const float* c1ab = (const float*)d_in[17];
    const float* c2aW = (const float*)d_in[18]; const float* c2ab = (const float*)d_in[19];
    const float* c1rW = (const float*)d_in[20]; const float* c1rb = (const float*)d_in[21];
    const float* c2rW = (const float*)d_in[22]; const float* c2rb = (const float*)d_in[23];
    float* out = (float*)d_out;

    cudaFuncSetAttribute(gemm_bf16x3, cudaFuncAttributeMaxDynamicSharedMemorySize, GSMEM);

    float* tagF = sym<float>(g_tag);
    float* t1F  = sym<float>(g_t1);
    float* lg   = sym<float>(g_lg);
    float* xw   = sym<float>(g_xw);
    __nv_bfloat16 *xH = sym<__nv_bfloat16>(g_xH), *xL = sym<__nv_bfloat16>(g_xL);
    __nv_bfloat16 *arcH = sym<__nv_bfloat16>(g_arcH), *arcL = sym<__nv_bfloat16>(g_arcL);
    __nv_bfloat16 *tagH = sym<__nv_bfloat16>(g_tagH), *tagL = sym<__nv_bfloat16>(g_tagL);
    __nv_bfloat16 *t1H = sym<__nv_bfloat16>(g_t1H), *t1L = sym<__nv_bfloat16>(g_t1L);
    __nv_bfloat16 *hH = sym<__nv_bfloat16>(g_hH), *hL = sym<__nv_bfloat16>(g_hL);
    __nv_bfloat16 *whaH = sym<__nv_bfloat16>(g_whaH), *whaL = sym<__nv_bfloat16>(g_whaL);
    __nv_bfloat16 *wdaH = sym<__nv_bfloat16>(g_wdaH), *wdaL = sym<__nv_bfloat16>(g_wdaL);
    __nv_bfloat16 *whtH = sym<__nv_bfloat16>(g_whtH), *whtL = sym<__nv_bfloat16>(g_whtL);
    __nv_bfloat16 *wdtH = sym<__nv_bfloat16>(g_wdtH), *wdtL = sym<__nv_bfloat16>(g_wdtL);
    __nv_bfloat16 *bilH = sym<__nv_bfloat16>(g_bilH), *bilL = sym<__nv_bfloat16>(g_bilL);
    __nv_bfloat16 *c1aH = sym<__nv_bfloat16>(g_c1aH), *c1aL = sym<__nv_bfloat16>(g_c1aL);
    __nv_bfloat16 *c2aH = sym<__nv_bfloat16>(g_c2aH), *c2aL = sym<__nv_bfloat16>(g_c2aL);
    __nv_bfloat16 *c1rH = sym<__nv_bfloat16>(g_c1rH), *c1rL = sym<__nv_bfloat16>(g_c1rL);
    __nv_bfloat16 *c2rH = sym<__nv_bfloat16>(g_c2rH), *c2rL = sym<__nv_bfloat16>(g_c2rL);

    __nv_bfloat16 *haH = arcH, *haL = arcL;
    __nv_bfloat16 *daH = arcH + (size_t)NROWS * ARCP, *daL = arcL + (size_t)NROWS * ARCP;
    __nv_bfloat16 *htH = tagH, *htL = tagL;
    __nv_bfloat16 *dtH = tagH + (size_t)NROWS * TAGP, *dtL = tagL + (size_t)NROWS * TAGP;
    float* htF = tagF;
    float* dtF = tagF + (size_t)NROWS * TAGP;

    // --- weight pad + split ([K,N] row-major) ---
    pad_split_w<<<(768 * 512 + 255) / 256, 256>>>(W_ha, 768, 500, 500, whaH, whaL, 768, 512);
    pad_split_w<<<(768 * 512 + 255) / 256, 256>>>(W_da, 768, 500, 500, wdaH, wdaL, 768, 512);
    pad_split_w<<<(768 * 128 + 255) / 256, 256>>>(W_ht, 768, 100, 100, whtH, whtL, 768, 128);
    pad_split_w<<<(768 * 128 + 255) / 256, 256>>>(W_dt, 768, 100, 100, wdtH, wdtL, 768, 128);
    for (int k = 0; k < 3; k++)
        pad_split_w<<<(512 * 512 + 255) / 256, 256>>>(bilW + (size_t)k * 501 * 501, 500, 501, 501,
                                                      bilH + (size_t)k * 512 * 512, bilL + (size_t)k * 512 * 512, 512, 512);
    pad_split_w<<<(512 * 512 + 255) / 256, 256>>>(c1aW, 500, 500, 500, c1aH, c1aL, 512, 512);
    pad_split_w<<<(512 * 512 + 255) / 256, 256>>>(c2aW, 500, 500, 500, c2aH, c2aL, 512, 512);
    pad_split_w<<<(128 * 128 + 255) / 256, 256>>>(c1rW, 100, 100, 100, c1rH, c1rL, 128, 128);
    pad_split_w<<<(128 * 128 + 255) / 256, 256>>>(c2rW, 100, 100, 100, c2rH, c2rL, 128, 128);

    // --- x + projections (fused bias+ELU+split epilogue) ---
    build_x_split<<<NROWS, 256>>>(inputs, sent, xH, xL);
    run_gemm(xH, xL, Dd, whaH, whaL, ARCP, nullptr, haH, haL, b_ha, ARCc, 1, NROWS, Dd);
    run_gemm(xH, xL, Dd, wdaH, wdaL, ARCP, nullptr, daH, daL, b_da, ARCc, 1, NROWS, Dd);
    run_gemm(xH, xL, Dd, whtH, whtL, TAGP, nullptr, htH, htL, b_ht, TAGc, 1, NROWS, Dd);
    run_gemm(xH, xL, Dd, wdtH, wdtL, TAGP, nullptr, dtH, dtL, b_dt, TAGc, 1, NROWS, Dd);

    dim3 bilgrid((SPc + 63) / 64, (SPc + 63) / 64, Bb);
    int smgrid = (NROWS + 7) / 8;

    for (int k = 0; k < 2; k++) {
        const float* biasT1 = bilW + (size_t)k * 501 * 501 + (size_t)500 * 501;
        run_gemm(haH, haL, ARCP, bilH + (size_t)k * 512 * 512, bilL + (size_t)k * 512 * 512, ARCP,
                 t1F, t1H, t1L, biasT1, 501, 0, NROWS, ARCP);
        bil_nt_bf16x3<<<bilgrid, 256>>>(t1H, t1L, t1F, daH, daL, bilb, k, lg);
        smax_topk<<<smgrid, 256>>>(lg);

        // arc streams
        run_gemm(arcH, arcL, ARCP, c1aH, c1aL, ARCP, xw, nullptr, nullptr, nullptr, 0, 0, 2 * NROWS, ARCP);
        gcn_agg_split<<<2 * NROWS, 128>>>(xw, c1ab, nullptr, hH, hL, ARCP, ARCc, 1);
        run_gemm(hH, hL, ARCP, c2aH, c2aL, ARCP, xw, nullptr, nullptr, nullptr, 0, 0, 2 * NROWS, ARCP);
        gcn_agg_split<<<2 * NROWS, 128>>>(xw, c2ab, nullptr, arcH, arcL, ARCP, ARCc, 0);
        // tag streams
        run_gemm(tagH, tagL, TAGP, c1rH, c1rL, TAGP, xw, nullptr, nullptr, nullptr, 0, 0, 2 * NROWS, TAGP);
        gcn_agg_split<<<2 * NROWS, 128>>>(xw, c1rb, nullptr, hH, hL, TAGP, TAGc, 1);
        run_gemm(hH, hL, TAGP, c2rH, c2rL, TAGP, xw, nullptr, nullptr, nullptr, 0, 0, 2 * NROWS, TAGP);
        gcn_agg_split<<<2 * NROWS, 128>>>(xw, c2rb, tagF, tagH, tagL, TAGP, TAGc, 0);
    }

    // final bilinear -> d_out
    {
        const float* biasT1 = bilW + (size_t)2 * 501 * 501 + (size_t)500 * 501;
        run_gemm(haH, haL, ARCP, bilH + (size_t)2 * 512 * 512, bilL + (size_t)2 * 512 * 512, ARCP,
                 t1F, t1H, t1L, biasT1, 501, 0, NROWS, ARCP);
        bil_nt_bf16x3<<<bilgrid, 256>>>(t1H, t1L, t1F, daH, daL, bilb, 2, out);
    }

    // append head_tag, dep_tag
    long arcN = (long)Bb * SPc * SPc;
    long tagN = (long)NROWS * TAGc;
    copy_strided<<<(unsigned)((tagN + 255) / 256), 256>>>(htF, out + arcN, TAGP, TAGc, NROWS);
    copy_strided<<<(unsigned)((tagN + 255) / 256), 256>>>(dtF, out + arcN + tagN, TAGP, TAGc, NROWS);
}

// round 8
// speedup vs baseline: 3.7057x; 1.0386x over previous
#include <cuda_runtime.h>
#include <cuda_bf16.h>
#include <math.h>
#include <mma.h>
#include <stdint.h>
using namespace nvcuda;

// ---------------- problem constants ----------------
static const int Bb   = 128;
static const int Ss   = 256;
static const int Dd   = 768;
static const int SPc  = 257;
static const int NROWS = Bb * SPc;           // 32896 = 257*128
static const int ARCc = 500;
static const int TAGc = 100;
static const int TOPKc = 8;
static const int ARCP = 512;
static const int TAGP = 128;
static const int PADR = 128;                 // row padding for unguarded bil loads

// main GEMM tiling: 128x128 CTA tile, 4 warps (64x64 each), k-chunk 32, 3-stage
static const int ASTR = 40;
static const int BSTR = 136;
static const int APL  = 128 * ASTR;
static const int BPL  = 32 * BSTR;
static const int STG  = 2 * APL + 2 * BPL;    // elems / stage
static const int NST  = 3;
static const int GSMEM = NST * STG * 2;       // 113664 B

// bil tiling: 128x128 tile, 4 warps (64x64), k-chunk 32, 2-stage
static const int BPLN = 128 * 40;             // elems per plane
static const int BSTG = 4 * BPLN;             // 4 planes / stage
static const int BILSMEM = 2 * BSTG * 2;      // 81920 B (Cs 128*132*4=67.6KB fits)

// ---------------- fp32 scratch ----------------
__device__ float g_tag [2 * NROWS * TAGP];
__device__ float g_t1  [NROWS * ARCP];
__device__ float g_lg  [Bb * SPc * SPc];
__device__ float g_xw  [2 * NROWS * ARCP];
__device__ float g_vals[NROWS * TOPKc];
__device__ int   g_idx [NROWS * TOPKc];
__device__ float g_dinv[NROWS];

// ---------------- bf16 hi/lo planes (padded rows for unguarded bil loads) ----
__device__ __align__(16) __nv_bfloat16 g_xH[NROWS * Dd],  g_xL[NROWS * Dd];
__device__ __align__(16) __nv_bfloat16 g_arcH[(2 * NROWS + PADR) * ARCP], g_arcL[(2 * NROWS + PADR) * ARCP];
__device__ __align__(16) __nv_bfloat16 g_tagH[2 * NROWS * TAGP], g_tagL[2 * NROWS * TAGP];
__device__ __align__(16) __nv_bfloat16 g_t1H[(NROWS + PADR) * ARCP], g_t1L[(NROWS + PADR) * ARCP];
__device__ __align__(16) __nv_bfloat16 g_hH[2 * NROWS * ARCP], g_hL[2 * NROWS * ARCP];
// weights [Kpad, Npad] row-major, padded, split
__device__ __align__(16) __nv_bfloat16 g_whaH[768 * 512], g_whaL[768 * 512];
__device__ __align__(16) __nv_bfloat16 g_wdaH[768 * 512], g_wdaL[768 * 512];
__device__ __align__(16) __nv_bfloat16 g_whtH[768 * 128], g_whtL[768 * 128];
__device__ __align__(16) __nv_bfloat16 g_wdtH[768 * 128], g_wdtL[768 * 128];
__device__ __align__(16) __nv_bfloat16 g_bilH[3 * 512 * 512], g_bilL[3 * 512 * 512];
__device__ __align__(16) __nv_bfloat16 g_c1aH[512 * 512], g_c1aL[512 * 512];
__device__ __align__(16) __nv_bfloat16 g_c2aH[512 * 512], g_c2aL[512 * 512];
__device__ __align__(16) __nv_bfloat16 g_c1rH[128 * 128], g_c1rL[128 * 128];
__device__ __align__(16) __nv_bfloat16 g_c2rH[128 * 128], g_c2rL[128 * 128];

__device__ __forceinline__ void splitbf(float v, __nv_bfloat16& h, __nv_bfloat16& l) {
    h = __float2bfloat16(v);
    l = __float2bfloat16(v - __bfloat162float(h));
}
__device__ __forceinline__ void cp16(void* dst, const void* src) {
    unsigned d = (unsigned)__cvta_generic_to_shared(dst);
    asm volatile("cp.async.cg.shared.global [%0], [%1], 16;" :: "r"(d), "l"(src));
}

// ---------------- fused weight pack (single launch) ----------------
struct PJob {
    const float* src; __nv_bfloat16* hi; __nv_bfloat16* lo;
    int Wr, Wc, ldw, Np; long base, end;
};
struct PTab { PJob j[11]; };

__global__ void pack_all(PTab t, long total) {
    long i = (long)blockIdx.x * blockDim.x + threadIdx.x;
    if (i >= total) return;
#pragma unroll
    for (int q = 0; q < 11; q++) {
        if (i < t.j[q].end) {
            long loc = i - t.j[q].base;
            int r = (int)(loc / t.j[q].Np), c = (int)(loc % t.j[q].Np);
            float v = (r < t.j[q].Wr && c < t.j[q].Wc) ? t.j[q].src[(size_t)r * t.j[q].ldw + c] : 0.f;
            splitbf(v, t.j[q].hi[loc], t.j[q].lo[loc]);
            return;
        }
    }
}

__global__ void build_x_split(const float* __restrict__ inp, const float* __restrict__ sent,
                              __nv_bfloat16* __restrict__ xh, __nv_bfloat16* __restrict__ xl) {
    int n = blockIdx.x;
    int b = n / SPc, r = n % SPc;
    const float* src = (r == 0) ? sent : (inp + ((size_t)b * Ss + (r - 1)) * Dd);
    for (int f = threadIdx.x; f < Dd; f += blockDim.x)
        splitbf(src[f], xh[(size_t)n * Dd + f], xl[(size_t)n * Dd + f]);
}

// ---------------- main GEMM: 3xBF16, 128x128, 4 warps 64x64, 3-stage, 1 sync/iter ----
__global__ void __launch_bounds__(128, 2)
gemm_bf16x3(const __nv_bfloat16* __restrict__ Ah, const __nv_bfloat16* __restrict__ Al, int lda,
            const __nv_bfloat16* __restrict__ Bh, const __nv_bfloat16* __restrict__ Bl, int ldb,
            float* __restrict__ Cf, int ldc,
            __nv_bfloat16* __restrict__ oH, __nv_bfloat16* __restrict__ oL,
            const float* __restrict__ bias, int validN, int act, int Kpad) {
    extern __shared__ __nv_bfloat16 sm[];
    int tid = threadIdx.x, warp = tid >> 5;
    int wm = warp & 1, wn = warp >> 1;
    int m0 = blockIdx.y << 7, n0 = blockIdx.x << 7;

    wmma::fragment<wmma::accumulator, 16, 16, 16, float> acc[4][4];
#pragma unroll
    for (int i = 0; i < 4; i++)
#pragma unroll
        for (int j = 0; j < 4; j++) wmma::fill_fragment(acc[i][j], 0.f);

    int nk = Kpad >> 5;

    auto load_stage = [&](int st, int k0) {
        __nv_bfloat16* a0 = sm + st * STG;
        __nv_bfloat16* a1 = a0 + APL;
        __nv_bfloat16* b0 = a1 + APL;
        __nv_bfloat16* b1 = b0 + BPL;
#pragma unroll
        for (int l = 0; l < 4; l++) {
            int id = tid + l * 128;
            int r = id >> 2, c = (id & 3) * 8;
            cp16(a0 + r * ASTR + c, Ah + (size_t)(m0 + r) * lda + k0 + c);
            cp16(a1 + r * ASTR + c, Al + (size_t)(m0 + r) * lda + k0 + c);
        }
#pragma unroll
        for (int l = 0; l < 4; l++) {
            int id = tid + l * 128;
            int r = id >> 4, c = (id & 15) * 8;
            cp16(b0 + r * BSTR + c, Bh + (size_t)(k0 + r) * ldb + n0 + c);
            cp16(b1 + r * BSTR + c, Bl + (size_t)(k0 + r) * ldb + n0 + c);
        }
        asm volatile("cp.async.commit_group;");
    };

    load_stage(0, 0);
    load_stage(1, 32);

    for (int kt = 0; kt < nk; kt++) {
        if (kt + 1 < nk) asm volatile("cp.async.wait_group 1;");
        else             asm volatile("cp.async.wait_group 0;");
        __syncthreads();
        if (kt + 2 < nk) load_stage((kt + 2) % NST, (kt + 2) << 5);

        int st = kt % NST;
        const __nv_bfloat16* a0 = sm + st * STG;
        const __nv_bfloat16* a1 = a0 + APL;
        const __nv_bfloat16* b0 = a1 + APL;
        const __nv_bfloat16* b1 = b0 + BPL;
#pragma unroll
        for (int ks = 0; ks < 2; ks++) {
            wmma::fragment<wmma::matrix_a, 16, 16, 16, __nv_bfloat16, wmma::row_major> fah[4], fal[4];
            wmma::fragment<wmma::matrix_b, 16, 16, 16, __nv_bfloat16, wmma::row_major> fbh[4], fbl[4];
#pragma unroll
            for (int i = 0; i < 4; i++) {
                wmma::load_matrix_sync(fah[i], a0 + (wm * 64 + i * 16) * ASTR + ks * 16, ASTR);
                wmma::load_matrix_sync(fal[i], a1 + (wm * 64 + i * 16) * ASTR + ks * 16, ASTR);
            }
#pragma unroll
            for (int j = 0; j < 4; j++) {
                wmma::load_matrix_sync(fbh[j], b0 + (ks * 16) * BSTR + wn * 64 + j * 16, BSTR);
                wmma::load_matrix_sync(fbl[j], b1 + (ks * 16) * BSTR + wn * 64 + j * 16, BSTR);
            }
#pragma unroll
            for (int i = 0; i < 4; i++)
#pragma unroll
                for (int j = 0; j < 4; j++) {
                    wmma::mma_sync(acc[i][j], fal[i], fbh[j], acc[i][j]);
                    wmma::mma_sync(acc[i][j], fah[i], fbl[j], acc[i][j]);
                    wmma::mma_sync(acc[i][j], fah[i], fbh[j], acc[i][j]);
                }
        }
        // no trailing sync: next iter's top barrier orders stage reuse (3 stages)
    }
    __syncthreads();   // protect smem reuse for epilogue

    float* Cs = (float*)sm;
#pragma unroll
    for (int i = 0; i < 4; i++)
#pragma unroll
        for (int j = 0; j < 4; j++)
            wmma::store_matrix_sync(Cs + (wm * 64 + i * 16) * 132 + wn * 64 + j * 16,
                                    acc[i][j], 132, wmma::mem_row_major);
    __syncthreads();
    {
        int c = tid;
        int gn = n0 + c;
        float bb = (bias && gn < validN) ? bias[gn] : 0.f;
#pragma unroll 8
        for (int r = 0; r < 128; r++) {
            float v = Cs[r * 132 + c] + bb;
            if (act) v = (v > 0.f) ? v : expm1f(v);
            size_t o = (size_t)(m0 + r) * ldc + gn;
            if (Cf) Cf[o] = v;
            if (oH) { __nv_bfloat16 h, l2; splitbf(v, h, l2); oH[o] = h; oL[o] = l2; }
        }
    }
}

// ---------------- batched bilinear NT: 128x128 tile, 4 warps 64x64, 2-stage cp.async ----
__global__ void __launch_bounds__(128, 2)
bil_nt_bf16x3(const __nv_bfloat16* __restrict__ t1h, const __nv_bfloat16* __restrict__ t1l,
              const float* __restrict__ t1f,
              const __nv_bfloat16* __restrict__ dah, const __nv_bfloat16* __restrict__ dal,
              const float* __restrict__ bilb, int kidx, float* __restrict__ Cout) {
    extern __shared__ __nv_bfloat16 sm[];
    int tid = threadIdx.x, warp = tid >> 5;
    int wm = warp & 1, wn = warp >> 1;
    int bz = blockIdx.z;
    int i0 = blockIdx.y << 7, j0 = blockIdx.x << 7;
    size_t arow = (size_t)bz * SPc + i0;     // global t1 row base (padded arrays: safe overread)
    size_t brow = (size_t)bz * SPc + j0;

    wmma::fragment<wmma::accumulator, 16, 16, 16, float> acc[4][4];
#pragma unroll
    for (int i = 0; i < 4; i++)
#pragma unroll
        for (int j = 0; j < 4; j++) wmma::fill_fragment(acc[i][j], 0.f);

    auto load_stage = [&](int st, int k0) {
        __nv_bfloat16* a0 = sm + st * BSTG;
        __nv_bfloat16* a1 = a0 + BPLN;
        __nv_bfloat16* b0 = a1 + BPLN;
        __nv_bfloat16* b1 = b0 + BPLN;
#pragma unroll
        for (int l = 0; l < 4; l++) {
            int id = tid + l * 128;
            int r = id >> 2, c = (id & 3) * 8;
            cp16(a0 + r * 40 + c, t1h + (arow + r) * ARCP + k0 + c);
            cp16(a1 + r * 40 + c, t1l + (arow + r) * ARCP + k0 + c);
            cp16(b0 + r * 40 + c, dah + (brow + r) * ARCP + k0 + c);
            cp16(b1 + r * 40 + c, dal + (brow + r) * ARCP + k0 + c);
        }
        asm volatile("cp.async.commit_group;");
    };

    const int nk = ARCP >> 5;   // 16
    load_stage(0, 0);
    load_stage(1, 32);

    for (int kt = 0; kt < nk; kt++) {
        if (kt + 1 < nk) asm volatile("cp.async.wait_group 1;");
        else             asm volatile("cp.async.wait_group 0;");
        __syncthreads();
        int st = kt & 1;
        const __nv_bfloat16* a0 = sm + st * BSTG;
        const __nv_bfloat16* a1 = a0 + BPLN;
        const __nv_bfloat16* b0 = a1 + BPLN;
        const __nv_bfloat16* b1 = b0 + BPLN;
#pragma unroll
        for (int ks = 0; ks < 2; ks++) {
            wmma::fragment<wmma::matrix_a, 16, 16, 16, __nv_bfloat16, wmma::row_major> fah[4], fal[4];
            wmma::fragment<wmma::matrix_b, 16, 16, 16, __nv_bfloat16, wmma::col_major> fbh[4], fbl[4];
#pragma unroll
            for (int i = 0; i < 4; i++) {
                wmma::load_matrix_sync(fah[i], a0 + (wm * 64 + i * 16) * 40 + ks * 16, 40);
                wmma::load_matrix_sync(fal[i], a1 + (wm * 64 + i * 16) * 40 + ks * 16, 40);
            }
#pragma unroll
            for (int j = 0; j < 4; j++) {
                wmma::load_matrix_sync(fbh[j], b0 + (wn * 64 + j * 16) * 40 + ks * 16, 40);
                wmma::load_matrix_sync(fbl[j], b1 + (wn * 64 + j * 16) * 40 + ks * 16, 40);
            }
#pragma unroll
            for (int i = 0; i < 4; i++)
#pragma unroll
                for (int j = 0; j < 4; j++) {
                    wmma::mma_sync(acc[i][j], fal[i], fbh[j], acc[i][j]);
                    wmma::mma_sync(acc[i][j], fah[i], fbl[j], acc[i][j]);
                    wmma::mma_sync(acc[i][j], fah[i], fbh[j], acc[i][j]);
                }
        }
        __syncthreads();
        if (kt + 2 < nk) load_stage(st, (kt + 2) << 5);
    }

    float* Cs = (float*)sm;
    __syncthreads();
#pragma unroll
    for (int i = 0; i < 4; i++)
#pragma unroll
        for (int j = 0; j < 4; j++)
            wmma::store_matrix_sync(Cs + (wm * 64 + i * 16) * 132 + wn * 64 + j * 16,
                                    acc[i][j], 132, wmma::mem_row_major);
    __syncthreads();
    {
        int c = tid;
        int oj = j0 + c;
        float bb = bilb[kidx];
        if (oj < SPc) {
            int rmax = SPc - i0; if (rmax > 128) rmax = 128;
            for (int r = 0; r < rmax; r++) {
                int oi = i0 + r;
                float rowb = t1f[((size_t)bz * SPc + oi) * ARCP + ARCc];
                Cout[((size_t)bz * SPc + oi) * SPc + oj] = Cs[r * 132 + c] + rowb + bb;
            }
        }
    }
}

// ---------------- fused softmax + top-8 + dinv ----------------
__global__ void smax_topk(const float* __restrict__ lg) {
    int row = blockIdx.x * 8 + (threadIdx.x >> 5);
    int lane = threadIdx.x & 31;
    if (row >= NROWS) return;
    const float* p = lg + (size_t)row * SPc;
    float v[9];
    float mx = -INFINITY;
#pragma unroll
    for (int t = 0; t < 9; t++) {
        int c = lane + 32 * t;
        v[t] = (c < SPc) ? p[c] : -INFINITY;
        mx = fmaxf(mx, v[t]);
    }
#pragma unroll
    for (int off = 16; off > 0; off >>= 1) mx = fmaxf(mx, __shfl_xor_sync(0xffffffffu, mx, off));
    float s = 0.f;
#pragma unroll
    for (int t = 0; t < 9; t++) {
        int c = lane + 32 * t;
        if (c < SPc) { v[t] = expf(v[t] - mx); s += v[t]; } else v[t] = -INFINITY;
    }
#pragma unroll
    for (int off = 16; off > 0; off >>= 1) s += __shfl_xor_sync(0xffffffffu, s, off);
    float inv = 1.f / s;
#pragma unroll
    for (int t = 0; t < 9; t++) {
        int c = lane + 32 * t;
        if (c < SPc) v[t] *= inv;
    }
    float acc8 = 0.f;
    for (int it = 0; it < TOPKc; it++) {
        float bv = -INFINITY; int bi = 0x7fffffff;
#pragma unroll
        for (int t = 0; t < 9; t++) {
            int c = lane + 32 * t;
            if (v[t] > bv || (v[t] == bv && c < bi)) { bv = v[t]; bi = c; }
        }
#pragma unroll
        for (int off = 16; off > 0; off >>= 1) {
            float ov = __shfl_down_sync(0xffffffffu, bv, off);
            int oi   = __shfl_down_sync(0xffffffffu, bi, off);
            if (ov > bv || (ov == bv && oi < bi)) { bv = ov; bi = oi; }
        }
        bv = __shfl_sync(0xffffffffu, bv, 0);
        bi = __shfl_sync(0xffffffffu, bi, 0);
        if (lane == 0) { g_vals[(size_t)row * TOPKc + it] = bv; g_idx[(size_t)row * TOPKc + it] = bi; }
        acc8 += bv;
        if (lane == (bi & 31)) v[bi >> 5] = -INFINITY;
    }
    if (lane == 0) g_dinv[row] = rsqrtf(1.f + acc8);
}

// ---------------- GCN aggregate + ELU + split (float4) ----------------
__global__ void gcn_agg_split(const float* __restrict__ xw, const float* __restrict__ bias,
                              float* __restrict__ outf,
                              __nv_bfloat16* __restrict__ outh, __nv_bfloat16* __restrict__ outl,
                              int Fp, int Fv, int act) {
    int gid = blockIdx.x;
    int i = gid % NROWS;
    int stream = gid / NROWS;
    int b = i / SPc;
    __shared__ float cf[TOPKc];
    __shared__ int   ss[TOPKc];
    float di = g_dinv[i];
    if (threadIdx.x < TOPKc) {
        int k = threadIdx.x;
        int srow = b * SPc + g_idx[(size_t)i * TOPKc + k];
        ss[k] = stream * NROWS + srow;
        cf[k] = di * g_vals[(size_t)i * TOPKc + k] * g_dinv[srow];
    }
    __syncthreads();
    float selfc = di * di;
    int nf4 = Fp >> 2;
    const float4* x4 = (const float4*)xw;
    for (int f = threadIdx.x; f < nf4; f += blockDim.x) {
        float4 a = x4[(size_t)gid * nf4 + f];
        float4 acc = make_float4(selfc * a.x, selfc * a.y, selfc * a.z, selfc * a.w);
#pragma unroll
        for (int k = 0; k < TOPKc; k++) {
            float4 sv = x4[(size_t)ss[k] * nf4 + f];
            float c = cf[k];
            acc.x += c * sv.x; acc.y += c * sv.y; acc.z += c * sv.z; acc.w += c * sv.w;
        }
        if (f * 4 < Fv) {
            float4 bv = ((const float4*)bias)[f];
            acc.x += bv.x; acc.y += bv.y; acc.z += bv.z; acc.w += bv.w;
        }
        if (act) {
            acc.x = (acc.x > 0.f) ? acc.x : expm1f(acc.x);
            acc.y = (acc.y > 0.f) ? acc.y : expm1f(acc.y);
            acc.z = (acc.z > 0.f) ? acc.z : expm1f(acc.z);
            acc.w = (acc.w > 0.f) ? acc.w : expm1f(acc.w);
        }
        size_t o = (size_t)gid * Fp + f * 4;
        if (outf) *(float4*)(outf + o) = acc;
        __nv_bfloat16 h0, l0, h1, l1, h2, l2, h3, l3;
        splitbf(acc.x, h0, l0); splitbf(acc.y, h1, l1);
        splitbf(acc.z, h2, l2); splitbf(acc.w, h3, l3);
        outh[o] = h0; outh[o + 1] = h1; outh[o + 2] = h2; outh[o + 3] = h3;
        outl[o] = l0; outl[o + 1] = l1; outl[o + 2] = l2; outl[o + 3] = l3;
    }
}

__global__ void copy_strided(const float* __restrict__ src, float* __restrict__ dst,
                             int ld, int valid, int rows) {
    long i = (long)blockIdx.x * blockDim.x + threadIdx.x;
    long total = (long)rows * valid;
    if (i >= total) return;
    int n = (int)(i / valid), f = (int)(i % valid);
    dst[i] = src[(size_t)n * ld + f];
}

// ---------------- host ----------------
template <typename T>
static T* sym(const void* s) { void* p; cudaGetSymbolAddress(&p, s); return (T*)p; }

static void run_gemm(const __nv_bfloat16* Ah, const __nv_bfloat16* Al, int lda,
                     const __nv_bfloat16* Bh, const __nv_bfloat16* Bl, int Npad,
                     float* Cf, __nv_bfloat16* oH, __nv_bfloat16* oL,
                     const float* bias, int validN, int act,
                     int M, int Kpad) {
    dim3 grid(Npad >> 7, M >> 7);
    gemm_bf16x3<<<grid, 128, GSMEM>>>(Ah, Al, lda, Bh, Bl, Npad, Cf, Npad, oH, oL, bias, validN, act, Kpad);
}

extern "C" void kernel_launch(void* const* d_in, const int* in_sizes, int n_in,
                              void* d_out, int out_size) {
    const float* inputs = (const float*)d_in[0];
    const float* sent   = (const float*)d_in[5];
    const float* W_ha = (const float*)d_in[6];  const float* b_ha = (const float*)d_in[7];
    const float* W_da = (const float*)d_in[8];  const float* b_da = (const float*)d_in[9];
    const float* W_ht = (const float*)d_in[10]; const float* b_ht = (const float*)d_in[11];
    const float* W_dt = (const float*)d_in[12]; const float* b_dt = (const float*)d_in[13];
    const float* bilW = (const float*)d_in[14]; const float* bilb = (const float*)d_in[15];
    const float* c1aW = (const float*)d_in[16]; const float* c1ab = (const float*)d_in[17];
    const float* c2aW = (const float*)d_in[18]; const float* c2ab = (const float*)d_in[19];
    const float* c1rW = (const float*)d_in[20]; const float* c1rb = (const float*)d_in[21];
    const float* c2rW = (const float*)d_in[22]; const float* c2rb = (const float*)d_in[23];
    float* out = (float*)d_out;

    cudaFuncSetAttribute(gemm_bf16x3, cudaFuncAttributeMaxDynamicSharedMemorySize, GSMEM);
    cudaFuncSetAttribute(bil_nt_bf16x3, cudaFuncAttributeMaxDynamicSharedMemorySize, BILSMEM);

    float* tagF = sym<float>(g_tag);
    float* t1F  = sym<float>(g_t1);
    float* lg   = sym<float>(g_lg);
    float* xw   = sym<float>(g_xw);
    __nv_bfloat16 *xH = sym<__nv_bfloat16>(g_xH), *xL = sym<__nv_bfloat16>(g_xL);
    __nv_bfloat16 *arcH = sym<__nv_bfloat16>(g_arcH), *arcL = sym<__nv_bfloat16>(g_arcL);
    __nv_bfloat16 *tagH = sym<__nv_bfloat16>(g_tagH), *tagL = sym<__nv_bfloat16>(g_tagL);
    __nv_bfloat16 *t1H = sym<__nv_bfloat16>(g_t1H), *t1L = sym<__nv_bfloat16>(g_t1L);
    __nv_bfloat16 *hH = sym<__nv_bfloat16>(g_hH), *hL = sym<__nv_bfloat16>(g_hL);
    __nv_bfloat16 *whaH = sym<__nv_bfloat16>(g_whaH), *whaL = sym<__nv_bfloat16>(g_whaL);
    __nv_bfloat16 *wdaH = sym<__nv_bfloat16>(g_wdaH), *wdaL = sym<__nv_bfloat16>(g_wdaL);
    __nv_bfloat16 *whtH = sym<__nv_bfloat16>(g_whtH), *whtL = sym<__nv_bfloat16>(g_whtL);
    __nv_bfloat16 *wdtH = sym<__nv_bfloat16>(g_wdtH), *wdtL = sym<__nv_bfloat16>(g_wdtL);
    __nv_bfloat16 *bilH = sym<__nv_bfloat16>(g_bilH), *bilL = sym<__nv_bfloat16>(g_bilL);
    __nv_bfloat16 *c1aH = sym<__nv_bfloat16>(g_c1aH), *c1aL = sym<__nv_bfloat16>(g_c1aL);
    __nv_bfloat16 *c2aH = sym<__nv_bfloat16>(g_c2aH), *c2aL = sym<__nv_bfloat16>(g_c2aL);
    __nv_bfloat16 *c1rH = sym<__nv_bfloat16>(g_c1rH), *c1rL = sym<__nv_bfloat16>(g_c1rL);
    __nv_bfloat16 *c2rH = sym<__nv_bfloat16>(g_c2rH), *c2rL = sym<__nv_bfloat16>(g_c2rL);

    __nv_bfloat16 *haH = arcH, *haL = arcL;
    __nv_bfloat16 *daH = arcH + (size_t)NROWS * ARCP, *daL = arcL + (size_t)NROWS * ARCP;
    __nv_bfloat16 *htH = tagH, *htL = tagL;
    __nv_bfloat16 *dtH = tagH + (size_t)NROWS * TAGP, *dtL = tagL + (size_t)NROWS * TAGP;
    float* htF = tagF;
    float* dtF = tagF + (size_t)NROWS * TAGP;

    // --- fused weight pack (ONE launch) ---
    {
        PTab t;
        long base = 0;
        auto add = [&](int q, const float* src, __nv_bfloat16* hi, __nv_bfloat16* lo,
                       int Wr, int Wc, int ldw, int Kp, int Np) {
            t.j[q] = {src, hi, lo, Wr, Wc, ldw, Np, base, base + (long)Kp * Np};
            base += (long)Kp * Np;
        };
        add(0, W_ha, whaH, whaL, 768, 500, 500, 768, 512);
        add(1, W_da, wdaH, wdaL, 768, 500, 500, 768, 512);
        add(2, W_ht, whtH, whtL, 768, 100, 100, 768, 128);
        add(3, W_dt, wdtH, wdtL, 768, 100, 100, 768, 128);
        for (int k = 0; k < 3; k++)
            add(4 + k, bilW + (size_t)k * 501 * 501, bilH + (size_t)k * 512 * 512,
                bilL + (size_t)k * 512 * 512, 500, 501, 501, 512, 512);
        add(7, c1aW, c1aH, c1aL, 500, 500, 500, 512, 512);
        add(8, c2aW, c2aH, c2aL, 500, 500, 500, 512, 512);
        add(9, c1rW, c1rH, c1rL, 100, 100, 100, 128, 128);
        add(10, c2rW, c2rH, c2rL, 100, 100, 100, 128, 128);
        pack_all<<<(unsigned)((base + 255) / 256), 256>>>(t, base);
    }

    // --- x + projections (tag first so ncu -s 5 lands on the da GEMM) ---
    build_x_split<<<NROWS, 256>>>(inputs, sent, xH, xL);
    run_gemm(xH, xL, Dd, whtH, whtL, TAGP, nullptr, htH, htL, b_ht, TAGc, 1, NROWS, Dd);
    run_gemm(xH, xL, Dd, wdtH, wdtL, TAGP, nullptr, dtH, dtL, b_dt, TAGc, 1, NROWS, Dd);
    run_gemm(xH, xL, Dd, whaH, whaL, ARCP, nullptr, haH, haL, b_ha, ARCc, 1, NROWS, Dd);
    run_gemm(xH, xL, Dd, wdaH, wdaL, ARCP, nullptr, daH, daL, b_da, ARCc, 1, NROWS, Dd);

    dim3 bilgrid((SPc + 127) / 128, (SPc + 127) / 128, Bb);
    int smgrid = (NROWS + 7) / 8;

    for (int k = 0; k < 2; k++) {
        const float* biasT1 = bilW + (size_t)k * 501 * 501 + (size_t)500 * 501;
        run_gemm(haH, haL, ARCP, bilH + (size_t)k * 512 * 512, bilL + (size_t)k * 512 * 512, ARCP,
                 t1F, t1H, t1L, biasT1, 501, 0, NROWS, ARCP);
        bil_nt_bf16x3<<<bilgrid, 128, BILSMEM>>>(t1H, t1L, t1F, daH, daL, bilb, k, lg);
        smax_topk<<<smgrid, 256>>>(lg);

        // arc streams ([ha;da] fused as [2N,512])
        run_gemm(arcH, arcL, ARCP, c1aH, c1aL, ARCP, xw, nullptr, nullptr, nullptr, 0, 0, 2 * NROWS, ARCP);
        gcn_agg_split<<<2 * NROWS, 128>>>(xw, c1ab, nullptr, hH, hL, ARCP, ARCc, 1);
        run_gemm(hH, hL, ARCP, c2aH, c2aL, ARCP, xw, nullptr, nullptr, nullptr, 0, 0, 2 * NROWS, ARCP);
        gcn_agg_split<<<2 * NROWS, 128>>>(xw, c2ab, nullptr, arcH, arcL, ARCP, ARCc, 0);
        // tag streams
        run_gemm(tagH, tagL, TAGP, c1rH, c1rL, TAGP, xw, nullptr, nullptr, nullptr, 0, 0, 2 * NROWS, TAGP);
        gcn_agg_split<<<2 * NROWS, 128>>>(xw, c1rb, nullptr, hH, hL, TAGP, TAGc, 1);
        run_gemm(hH, hL, TAGP, c2rH, c2rL, TAGP, xw, nullptr, nullptr, nullptr, 0, 0, 2 * NROWS, TAGP);
        gcn_agg_split<<<2 * NROWS, 128>>>(xw, c2rb, tagF, tagH, tagL, TAGP, TAGc, 0);
    }

    // final bilinear -> d_out
    {
        const float* biasT1 = bilW + (size_t)2 * 501 * 501 + (size_t)500 * 501;
        run_gemm(haH, haL, ARCP, bilH + (size_t)2 * 512 * 512, bilL + (size_t)2 * 512 * 512, ARCP,
                 t1F, t1H, t1L, biasT1, 501, 0, NROWS, ARCP);
        bil_nt_bf16x3<<<bilgrid, 128, BILSMEM>>>(t1H, t1L, t1F, daH, daL, bilb, 2, out);
    }

    // append head_tag, dep_tag
    long arcN = (long)Bb * SPc * SPc;
    long tagN = (long)NROWS * TAGc;
    copy_strided<<<(unsigned)((tagN + 255) / 256), 256>>>(htF, out + arcN, TAGP, TAGc, NROWS);
    copy_strided<<<(unsigned)((tagN + 255) / 256), 256>>>(dtF, out + arcN + tagN, TAGP, TAGc, NROWS);
}